// round 2
// baseline (speedup 1.0000x reference)
#include <cuda_runtime.h>
#include <math.h>

// Problem dims (fixed by the dataset)
#define BQ 128
#define NQ 512
#define HQ 128
#define M2 65536            // BQ*NQ rows for gate GEMMs
#define ELEMS 8388608       // M2*HQ

// Scratch (allocation-free rule: __device__ globals)
__device__ float g_a [ELEMS];
__device__ float g_z [ELEMS];
__device__ float g_rh[ELEMS];
__device__ float g_h0[ELEMS];
__device__ float g_h1[ELEMS];

// ---------------------------------------------------------------------------
// Kernel 1: a[b,n,h] = sum_m A[b,m,n] * hprev[b,m,h] + b_ah[h]
// Both operands are k(=m)-major in global memory -> no transposes needed.
// Block tile: 64 (n) x 128 (h), K-chunk 32. 256 threads, 8x4 micro-tile.
// ---------------------------------------------------------------------------
__global__ __launch_bounds__(256)
void k_gemm_a(const float* __restrict__ A,
              const float* __restrict__ hidden_in,
              const float* __restrict__ b_ah,
              int hsel)
{
    __shared__ float As[32][64];    // [k][n]
    __shared__ float Hs[32][128];   // [k][h]

    const float* hp;
    if (hsel == 0)      hp = hidden_in;
    else if (hsel == 1) hp = g_h0;
    else                hp = g_h1;

    const int b  = blockIdx.y;
    const int n0 = blockIdx.x * 64;
    const int t  = threadIdx.x;
    const int mh = t & 31;   // h micro-col group (4 cols)
    const int mn = t >> 5;   // n micro-row group (8 rows)

    const float* Ab = A  + (size_t)b * NQ * NQ;
    const float* Hb = hp + (size_t)b * NQ * HQ;

    float acc[8][4];
#pragma unroll
    for (int i = 0; i < 8; i++)
#pragma unroll
        for (int j = 0; j < 4; j++) acc[i][j] = 0.f;

    for (int kc = 0; kc < NQ; kc += 32) {
        // Load A tile: 32 rows x 64 cols (coalesced float4)
        {
            const int c  = t & 15;        // float4 col 0..15
            const int k0 = t >> 4;        // 0..15, two passes
            const float4* s0 = reinterpret_cast<const float4*>(Ab + (size_t)(kc + k0) * NQ + n0);
            *reinterpret_cast<float4*>(&As[k0][c * 4]) = s0[c];
            const float4* s1 = reinterpret_cast<const float4*>(Ab + (size_t)(kc + k0 + 16) * NQ + n0);
            *reinterpret_cast<float4*>(&As[k0 + 16][c * 4]) = s1[c];
        }
        // Load H tile: 32 rows x 128 cols (coalesced float4)
        {
            const int c  = t & 31;        // float4 col 0..31
            const int k0 = t >> 5;        // 0..7, four passes
#pragma unroll
            for (int p = 0; p < 4; p++) {
                const float4* s = reinterpret_cast<const float4*>(Hb + (size_t)(kc + k0 + p * 8) * HQ);
                *reinterpret_cast<float4*>(&Hs[k0 + p * 8][c * 4]) = s[c];
            }
        }
        __syncthreads();

#pragma unroll
        for (int k = 0; k < 32; k++) {
            const float4 a0 = *reinterpret_cast<const float4*>(&As[k][mn * 8]);     // broadcast
            const float4 a1 = *reinterpret_cast<const float4*>(&As[k][mn * 8 + 4]); // broadcast
            const float4 hv = *reinterpret_cast<const float4*>(&Hs[k][mh * 4]);     // lane-wise, conflict-free
            const float av[8] = {a0.x, a0.y, a0.z, a0.w, a1.x, a1.y, a1.z, a1.w};
#pragma unroll
            for (int ii = 0; ii < 8; ii++) {
                acc[ii][0] = fmaf(av[ii], hv.x, acc[ii][0]);
                acc[ii][1] = fmaf(av[ii], hv.y, acc[ii][1]);
                acc[ii][2] = fmaf(av[ii], hv.z, acc[ii][2]);
                acc[ii][3] = fmaf(av[ii], hv.w, acc[ii][3]);
            }
        }
        __syncthreads();
    }

    const float4 bb = *reinterpret_cast<const float4*>(b_ah + mh * 4);
    float* outb = g_a + (size_t)b * NQ * HQ;
#pragma unroll
    for (int ii = 0; ii < 8; ii++) {
        const int n = n0 + mn * 8 + ii;
        float4 v;
        v.x = acc[ii][0] + bb.x;
        v.y = acc[ii][1] + bb.y;
        v.z = acc[ii][2] + bb.z;
        v.w = acc[ii][3] + bb.w;
        *reinterpret_cast<float4*>(outb + (size_t)n * HQ + mh * 4) = v;
    }
}

// ---------------------------------------------------------------------------
// Kernel 2: out = epilogue( X1 @ W1^T + X2 @ W2^T + bias1 + bias2 )
//   MODE 0 (z):  sigmoid -> g_z
//   MODE 1 (r):  sigmoid * hprev -> g_rh
//   MODE 2 (c):  tanh; h' = (1-z)*h + z*c -> selected h buffer / d_out
// X1 = g_a always.  X2 = hprev (MODE 0/1) or g_rh (MODE 2).
// Block tile: 64 rows x 128 cols, K=128 in chunks of 32. 256 threads, 8x4.
// Both smem tiles stored k-major (transposed on store) so the inner loop is
// 2 broadcast LDS.128 + 1 conflict-free lane-wise LDS.128 per k.
// ---------------------------------------------------------------------------
template<int MODE>
__global__ __launch_bounds__(256)
void k_gate(const float* __restrict__ W1,
            const float* __restrict__ W2,
            const float* __restrict__ bias1,
            const float* __restrict__ bias2,
            const float* __restrict__ hidden_in,
            int hsel,
            float* __restrict__ dout,
            int osel)
{
    __shared__ float Xs[32][64];    // [k][i]
    __shared__ float Ws[32][128];   // [k][j]

    const float* hp;
    if (hsel == 0)      hp = hidden_in;
    else if (hsel == 1) hp = g_h0;
    else                hp = g_h1;

    const float* X2 = (MODE == 2) ? g_rh : hp;

    float* outp;
    if (MODE == 0)      outp = g_z;
    else if (MODE == 1) outp = g_rh;
    else                outp = (osel == 0) ? g_h0 : (osel == 1 ? g_h1 : dout);

    const int i0 = blockIdx.x * 64;
    const int t  = threadIdx.x;
    const int mh = t & 31;
    const int mn = t >> 5;

    float acc[8][4];
#pragma unroll
    for (int i = 0; i < 8; i++)
#pragma unroll
        for (int j = 0; j < 4; j++) acc[i][j] = 0.f;

#pragma unroll
    for (int g = 0; g < 2; g++) {
        const float* X = g ? X2 : g_a;
        const float* W = g ? W2 : W1;
#pragma unroll
        for (int kc = 0; kc < HQ; kc += 32) {
            // X chunk [64 i][32 k] -> Xs[k][i] (transpose on store)
            {
                const int k4 = t & 7;        // float4 index over k
                const int il = t >> 3;       // 0..31, two passes
#pragma unroll
                for (int p = 0; p < 2; p++) {
                    const int i = il + p * 32;
                    const float4 v = *reinterpret_cast<const float4*>(
                        X + (size_t)(i0 + i) * HQ + kc + k4 * 4);
                    Xs[k4 * 4 + 0][i] = v.x;
                    Xs[k4 * 4 + 1][i] = v.y;
                    Xs[k4 * 4 + 2][i] = v.z;
                    Xs[k4 * 4 + 3][i] = v.w;
                }
            }
            // W chunk [128 j][32 k] -> Ws[k][j] (transpose on store)
            {
                const int k4 = t & 7;
                const int jl = t >> 3;
#pragma unroll
                for (int p = 0; p < 4; p++) {
                    const int j = jl + p * 32;
                    const float4 v = *reinterpret_cast<const float4*>(
                        W + (size_t)j * HQ + kc + k4 * 4);
                    Ws[k4 * 4 + 0][j] = v.x;
                    Ws[k4 * 4 + 1][j] = v.y;
                    Ws[k4 * 4 + 2][j] = v.z;
                    Ws[k4 * 4 + 3][j] = v.w;
                }
            }
            __syncthreads();

#pragma unroll
            for (int k = 0; k < 32; k++) {
                const float4 x0 = *reinterpret_cast<const float4*>(&Xs[k][mn * 8]);
                const float4 x1 = *reinterpret_cast<const float4*>(&Xs[k][mn * 8 + 4]);
                const float4 wv = *reinterpret_cast<const float4*>(&Ws[k][mh * 4]);
                const float xv[8] = {x0.x, x0.y, x0.z, x0.w, x1.x, x1.y, x1.z, x1.w};
#pragma unroll
                for (int ii = 0; ii < 8; ii++) {
                    acc[ii][0] = fmaf(xv[ii], wv.x, acc[ii][0]);
                    acc[ii][1] = fmaf(xv[ii], wv.y, acc[ii][1]);
                    acc[ii][2] = fmaf(xv[ii], wv.z, acc[ii][2]);
                    acc[ii][3] = fmaf(xv[ii], wv.w, acc[ii][3]);
                }
            }
            __syncthreads();
        }
    }

    const float4 b1 = *reinterpret_cast<const float4*>(bias1 + mh * 4);
    const float4 b2 = *reinterpret_cast<const float4*>(bias2 + mh * 4);
    const float bj[4] = {b1.x + b2.x, b1.y + b2.y, b1.z + b2.z, b1.w + b2.w};

#pragma unroll
    for (int ii = 0; ii < 8; ii++) {
        const int i = i0 + mn * 8 + ii;
        const size_t off = (size_t)i * HQ + mh * 4;
        float v[4];
#pragma unroll
        for (int jj = 0; jj < 4; jj++) v[jj] = acc[ii][jj] + bj[jj];

        if (MODE == 0) {            // z = sigmoid(.)
#pragma unroll
            for (int jj = 0; jj < 4; jj++)
                v[jj] = 1.f / (1.f + __expf(-v[jj]));
        } else if (MODE == 1) {     // rh = sigmoid(.) * h
            const float4 hv = *reinterpret_cast<const float4*>(hp + off);
            const float hh[4] = {hv.x, hv.y, hv.z, hv.w};
#pragma unroll
            for (int jj = 0; jj < 4; jj++)
                v[jj] = hh[jj] * (1.f / (1.f + __expf(-v[jj])));
        } else {                    // h' = (1-z)h + z*tanh(.)
            const float4 hv = *reinterpret_cast<const float4*>(hp + off);
            const float4 zz = *reinterpret_cast<const float4*>(g_z + off);
            const float hh[4] = {hv.x, hv.y, hv.z, hv.w};
            const float zv[4] = {zz.x, zz.y, zz.z, zz.w};
#pragma unroll
            for (int jj = 0; jj < 4; jj++) {
                const float c = tanhf(v[jj]);
                v[jj] = (1.f - zv[jj]) * hh[jj] + zv[jj] * c;
            }
        }
        *reinterpret_cast<float4*>(outp + off) = make_float4(v[0], v[1], v[2], v[3]);
    }
}

// ---------------------------------------------------------------------------
// Host launcher: 4 steps x (a-GEMM, z, r->rh, c->h'). Graph-capturable:
// kernel launches on the default stream only, no sync, no allocation.
// ---------------------------------------------------------------------------
extern "C" void kernel_launch(void* const* d_in, const int* in_sizes, int n_in,
                              void* d_out, int out_size)
{
    const float* A      = (const float*)d_in[0];
    const float* hidden = (const float*)d_in[1];
    const float* b_ah   = (const float*)d_in[2];
    const float* w_z    = (const float*)d_in[3];
    const float* b_wz   = (const float*)d_in[4];
    const float* u_z    = (const float*)d_in[5];
    const float* b_uz   = (const float*)d_in[6];
    const float* w_r    = (const float*)d_in[7];
    const float* b_wr   = (const float*)d_in[8];
    const float* u_r    = (const float*)d_in[9];
    const float* b_ur   = (const float*)d_in[10];
    const float* w      = (const float*)d_in[11];
    const float* b_w    = (const float*)d_in[12];
    const float* u      = (const float*)d_in[13];
    const float* b_u    = (const float*)d_in[14];
    float* out = (float*)d_out;

    // hsel: which buffer holds h_prev for this step (0=input,1=g_h0,2=g_h1)
    // osel: where MODE 2 writes h_next (0=g_h0,1=g_h1,2=d_out)
    const int hsels[4] = {0, 1, 2, 1};
    const int osels[4] = {0, 1, 0, 2};

    const dim3 gridA(NQ / 64, BQ);
    const dim3 gridG(M2 / 64);

    for (int s = 0; s < 4; s++) {
        const int hs = hsels[s];
        const int os = osels[s];
        k_gemm_a<<<gridA, 256>>>(A, hidden, b_ah, hs);
        k_gate<0><<<gridG, 256>>>(w_z, u_z, b_wz, b_uz, hidden, hs, out, os);
        k_gate<1><<<gridG, 256>>>(w_r, u_r, b_wr, b_ur, hidden, hs, out, os);
        k_gate<2><<<gridG, 256>>>(w,   u,   b_w,  b_u,  hidden, hs, out, os);
    }
}

// round 5
// speedup vs baseline: 1.3672x; 1.3672x over previous
#include <cuda_runtime.h>
#include <math.h>
#include <stdint.h>

#define BQ 128
#define NQ 512
#define HQ 128
#define M2 65536

// ---------------- scratch (allocation-free rule) ----------------
__device__ float g_a [(size_t)M2 * HQ];
__device__ float g_z [(size_t)M2 * HQ];
__device__ float g_rh[(size_t)M2 * HQ];
__device__ float g_h0[(size_t)M2 * HQ];
__device__ float g_h1[(size_t)M2 * HQ];

// ---------------- helpers ----------------
__device__ __forceinline__ void cpa16(uint32_t dst, const float* src) {
    asm volatile("cp.async.cg.shared.global [%0], [%1], 16;" :: "r"(dst), "l"(src));
}
#define CP_COMMIT() asm volatile("cp.async.commit_group;" ::: "memory")
#define CP_WAIT1()  asm volatile("cp.async.wait_group 1;" ::: "memory")
#define CP_WAIT0()  asm volatile("cp.async.wait_group 0;" ::: "memory")

__device__ __forceinline__ uint32_t smem_u32(const void* p) {
    uint32_t a;
    asm("{ .reg .u64 t; cvta.to.shared.u64 t, %1; cvt.u32.u64 %0, t; }" : "=r"(a) : "l"(p));
    return a;
}
__device__ __forceinline__ uint32_t f2tf(float x) {
    uint32_t r;
    asm("cvt.rna.tf32.f32 %0, %1;" : "=r"(r) : "f"(x));
    return r;
}
// Split fp32 into tf32 hi + tf32 lo (residual). hi bits are a valid fp32.
__device__ __forceinline__ void split_tf(float x, uint32_t& hi, uint32_t& lo) {
    hi = f2tf(x);
    lo = f2tf(x - __uint_as_float(hi));
}
__device__ __forceinline__ void mma8(float* c, const uint32_t* a, const uint32_t* b) {
    asm volatile(
        "mma.sync.aligned.m16n8k8.row.col.f32.tf32.tf32.f32 "
        "{%0,%1,%2,%3}, {%4,%5,%6,%7}, {%8,%9}, {%0,%1,%2,%3};"
        : "+f"(c[0]), "+f"(c[1]), "+f"(c[2]), "+f"(c[3])
        : "r"(a[0]), "r"(a[1]), "r"(a[2]), "r"(a[3]), "r"(b[0]), "r"(b[1]));
}

// K-major tile loader: 32 k-rows x 128 floats -> smem [k][i], stride 136 (pad)
__device__ __forceinline__ void load_km(uint32_t sb, const float* src, int stride, int t) {
    const int k  = t >> 3;
    const int c4 = t & 7;
#pragma unroll
    for (int p = 0; p < 4; p++) {
        const int c = c4 + p * 8;   // float4 index 0..31
        cpa16(sb + (uint32_t)(k * 136 + c * 4) * 4, src + (size_t)k * stride + c * 4);
    }
}
// M-major tile loader: 128 i-rows x 32 floats -> smem [i][k], stride 36 (pad)
__device__ __forceinline__ void load_mm(uint32_t sb, const float* src, int stride, int t) {
#pragma unroll
    for (int p = 0; p < 4; p++) {
        const int idx = t + p * 256;     // 0..1023
        const int i  = idx >> 3;
        const int f4 = idx & 7;
        cpa16(sb + (uint32_t)(i * 36 + f4 * 4) * 4, src + (size_t)i * stride + f4 * 4);
    }
}

#define SMEM_A_BYTES (2 * 2 * 32 * 136 * 4)    // 69632
#define SMEM_G_BYTES (2 * 2 * 128 * 36 * 4)    // 73728

// ---------------------------------------------------------------------------
// a-GEMM: a[b,n,h] = sum_m A[b,m,n] * hprev[b,m,h] + b_ah[h]
// CTA tile 128(n) x 128(h), K=512 in 16 chunks of 32. K-major smem, stride 136.
// 3xTF32: D += Ahi*Bhi + Ahi*Blo + Alo*Bhi  (fp32-grade accuracy)
// ---------------------------------------------------------------------------
__global__ __launch_bounds__(256)
void k_mma_a(const float* __restrict__ A, const float* __restrict__ hp,
             const float* __restrict__ bias, float* __restrict__ outp)
{
    extern __shared__ float smem[];
    const uint32_t sb = smem_u32(smem);
    const int t = threadIdx.x, lane = t & 31, wid = t >> 5;
    const int wi = wid & 1, wj = wid >> 1;           // 2 x 4 warps
    const int g = lane >> 2, tq = lane & 3;
    const int b = blockIdx.y, n0 = blockIdx.x * 128;

    const float* Ab = A  + (size_t)b * NQ * NQ + n0;
    const float* Hb = hp + (size_t)b * NQ * HQ;

    float acc[4][4][4];
#pragma unroll
    for (int a_ = 0; a_ < 4; a_++)
#pragma unroll
        for (int b_ = 0; b_ < 4; b_++)
#pragma unroll
            for (int c_ = 0; c_ < 4; c_++) acc[a_][b_][c_] = 0.f;

    const int C = 16;
    load_km(sb,          Ab, NQ, t);
    load_km(sb + 17408u, Hb, HQ, t);
    CP_COMMIT();

    for (int c = 0; c < C; c++) {
        if (c + 1 < C) {
            const uint32_t s = (uint32_t)((c + 1) & 1) * 34816u;
            load_km(sb + s,          Ab + (size_t)(c + 1) * 32 * NQ, NQ, t);
            load_km(sb + s + 17408u, Hb + (size_t)(c + 1) * 32 * HQ, HQ, t);
            CP_COMMIT();
            CP_WAIT1();
        } else {
            CP_WAIT0();
        }
        __syncthreads();
        const float* Xs = smem + (c & 1) * 8704;     // floats per buffer
        const float* Ws = Xs + 4352;
#pragma unroll
        for (int kb = 0; kb < 32; kb += 8) {
            uint32_t ah[4][4], al[4][4], bh[4][2], bl[4][2];
#pragma unroll
            for (int mf = 0; mf < 4; mf++) {
                const int r = wi * 64 + mf * 16 + g;
                split_tf(Xs[(kb + tq) * 136 + r],         ah[mf][0], al[mf][0]);
                split_tf(Xs[(kb + tq) * 136 + r + 8],     ah[mf][1], al[mf][1]);
                split_tf(Xs[(kb + tq + 4) * 136 + r],     ah[mf][2], al[mf][2]);
                split_tf(Xs[(kb + tq + 4) * 136 + r + 8], ah[mf][3], al[mf][3]);
            }
#pragma unroll
            for (int nf = 0; nf < 4; nf++) {
                const int cj = wj * 32 + nf * 8 + g;
                split_tf(Ws[(kb + tq) * 136 + cj],     bh[nf][0], bl[nf][0]);
                split_tf(Ws[(kb + tq + 4) * 136 + cj], bh[nf][1], bl[nf][1]);
            }
#pragma unroll
            for (int mf = 0; mf < 4; mf++)
#pragma unroll
                for (int nf = 0; nf < 4; nf++) {
                    mma8(acc[mf][nf], al[mf], bh[nf]);
                    mma8(acc[mf][nf], ah[mf], bl[nf]);
                    mma8(acc[mf][nf], ah[mf], bh[nf]);
                }
        }
        __syncthreads();
    }

    float* ob = outp + (size_t)b * NQ * HQ;
#pragma unroll
    for (int mf = 0; mf < 4; mf++) {
#pragma unroll
        for (int h2 = 0; h2 < 2; h2++) {
            const int i = n0 + wi * 64 + mf * 16 + g + h2 * 8;
            float* orow = ob + (size_t)i * HQ;
#pragma unroll
            for (int nf = 0; nf < 4; nf++) {
                const int j = wj * 32 + nf * 8 + 2 * tq;
                const float2 bb = *reinterpret_cast<const float2*>(bias + j);
                float2 v;
                v.x = acc[mf][nf][h2 * 2 + 0] + bb.x;
                v.y = acc[mf][nf][h2 * 2 + 1] + bb.y;
                *reinterpret_cast<float2*>(orow + j) = v;
            }
        }
    }
}

// ---------------------------------------------------------------------------
// Gate GEMM: D[i,j] = X1[i,:]W1[j,:] + X2[i,:]W2[j,:]; fused GRU epilogue.
//   MODE 0: out = sigmoid(D+b1+b2)            (z)
//   MODE 1: out = sigmoid(D+b1+b2) * hp       (r*h)
//   MODE 2: out = (1-z)*hp + z*tanh(D+b1+b2)  (h')
// CTA tile 128 x 128, K = 2 x 128 in 8 chunks of 32. M-major smem, stride 36.
// ---------------------------------------------------------------------------
template<int MODE>
__global__ __launch_bounds__(256)
void k_gate(const float* __restrict__ X1, const float* __restrict__ X2,
            const float* __restrict__ W1, const float* __restrict__ W2,
            const float* __restrict__ b1, const float* __restrict__ b2,
            const float* __restrict__ hp, const float* __restrict__ zp,
            float* __restrict__ outp)
{
    extern __shared__ float smem[];
    const uint32_t sb = smem_u32(smem);
    const int t = threadIdx.x, lane = t & 31, wid = t >> 5;
    const int wi = wid & 1, wj = wid >> 1;
    const int g = lane >> 2, tq = lane & 3;
    const int i0 = blockIdx.x * 128;

    const float* xs[2] = { X1 + (size_t)i0 * HQ, X2 + (size_t)i0 * HQ };
    const float* ws[2] = { W1, W2 };

    float acc[4][4][4];
#pragma unroll
    for (int a_ = 0; a_ < 4; a_++)
#pragma unroll
        for (int b_ = 0; b_ < 4; b_++)
#pragma unroll
            for (int c_ = 0; c_ < 4; c_++) acc[a_][b_][c_] = 0.f;

    const int C = 8;
    load_mm(sb,          xs[0], HQ, t);
    load_mm(sb + 18432u, ws[0], HQ, t);
    CP_COMMIT();

    for (int c = 0; c < C; c++) {
        if (c + 1 < C) {
            const uint32_t s = (uint32_t)((c + 1) & 1) * 36864u;
            const int gg = (c + 1) >> 2;
            const int kc = ((c + 1) & 3) * 32;
            load_mm(sb + s,          xs[gg] + kc, HQ, t);
            load_mm(sb + s + 18432u, ws[gg] + kc, HQ, t);
            CP_COMMIT();
            CP_WAIT1();
        } else {
            CP_WAIT0();
        }
        __syncthreads();
        const float* Xs = smem + (c & 1) * 9216;     // floats per buffer
        const float* Ws = Xs + 4608;
#pragma unroll
        for (int kb = 0; kb < 32; kb += 8) {
            uint32_t ah[4][4], al[4][4], bh[4][2], bl[4][2];
#pragma unroll
            for (int mf = 0; mf < 4; mf++) {
                const int r = wi * 64 + mf * 16 + g;
                split_tf(Xs[r * 36 + kb + tq],           ah[mf][0], al[mf][0]);
                split_tf(Xs[(r + 8) * 36 + kb + tq],     ah[mf][1], al[mf][1]);
                split_tf(Xs[r * 36 + kb + tq + 4],       ah[mf][2], al[mf][2]);
                split_tf(Xs[(r + 8) * 36 + kb + tq + 4], ah[mf][3], al[mf][3]);
            }
#pragma unroll
            for (int nf = 0; nf < 4; nf++) {
                const int cj = wj * 32 + nf * 8 + g;
                split_tf(Ws[cj * 36 + kb + tq],     bh[nf][0], bl[nf][0]);
                split_tf(Ws[cj * 36 + kb + tq + 4], bh[nf][1], bl[nf][1]);
            }
#pragma unroll
            for (int mf = 0; mf < 4; mf++)
#pragma unroll
                for (int nf = 0; nf < 4; nf++) {
                    mma8(acc[mf][nf], al[mf], bh[nf]);
                    mma8(acc[mf][nf], ah[mf], bl[nf]);
                    mma8(acc[mf][nf], ah[mf], bh[nf]);
                }
        }
        __syncthreads();
    }

#pragma unroll
    for (int mf = 0; mf < 4; mf++) {
#pragma unroll
        for (int h2 = 0; h2 < 2; h2++) {
            const int i = i0 + wi * 64 + mf * 16 + g + h2 * 8;
            const size_t rb = (size_t)i * HQ;
#pragma unroll
            for (int nf = 0; nf < 4; nf++) {
                const int j = wj * 32 + nf * 8 + 2 * tq;
                const float2 bb1 = *reinterpret_cast<const float2*>(b1 + j);
                const float2 bb2 = *reinterpret_cast<const float2*>(b2 + j);
                float v0 = acc[mf][nf][h2 * 2 + 0] + bb1.x + bb2.x;
                float v1 = acc[mf][nf][h2 * 2 + 1] + bb1.y + bb2.y;
                float2 o;
                if (MODE == 0) {
                    o.x = 1.f / (1.f + __expf(-v0));
                    o.y = 1.f / (1.f + __expf(-v1));
                } else if (MODE == 1) {
                    const float2 hv = *reinterpret_cast<const float2*>(hp + rb + j);
                    o.x = hv.x * (1.f / (1.f + __expf(-v0)));
                    o.y = hv.y * (1.f / (1.f + __expf(-v1)));
                } else {
                    const float2 hv = *reinterpret_cast<const float2*>(hp + rb + j);
                    const float2 zz = *reinterpret_cast<const float2*>(zp + rb + j);
                    o.x = (1.f - zz.x) * hv.x + zz.x * tanhf(v0);
                    o.y = (1.f - zz.y) * hv.y + zz.y * tanhf(v1);
                }
                *reinterpret_cast<float2*>(outp + rb + j) = o;
            }
        }
    }
}

// ---------------------------------------------------------------------------
// Host launcher: 4 steps x (a-GEMM, z, r->rh, c->h'). Graph-capturable.
// ---------------------------------------------------------------------------
extern "C" void kernel_launch(void* const* d_in, const int* in_sizes, int n_in,
                              void* d_out, int out_size)
{
    const float* A      = (const float*)d_in[0];
    const float* hidden = (const float*)d_in[1];
    const float* b_ah   = (const float*)d_in[2];
    const float* w_z    = (const float*)d_in[3];
    const float* b_wz   = (const float*)d_in[4];
    const float* u_z    = (const float*)d_in[5];
    const float* b_uz   = (const float*)d_in[6];
    const float* w_r    = (const float*)d_in[7];
    const float* b_wr   = (const float*)d_in[8];
    const float* u_r    = (const float*)d_in[9];
    const float* b_ur   = (const float*)d_in[10];
    const float* w      = (const float*)d_in[11];
    const float* b_w    = (const float*)d_in[12];
    const float* u      = (const float*)d_in[13];
    const float* b_u    = (const float*)d_in[14];
    float* out = (float*)d_out;

    float *ga, *gz, *grh, *h0, *h1;
    cudaGetSymbolAddress((void**)&ga,  g_a);
    cudaGetSymbolAddress((void**)&gz,  g_z);
    cudaGetSymbolAddress((void**)&grh, g_rh);
    cudaGetSymbolAddress((void**)&h0,  g_h0);
    cudaGetSymbolAddress((void**)&h1,  g_h1);

    cudaFuncSetAttribute(k_mma_a,   cudaFuncAttributeMaxDynamicSharedMemorySize, SMEM_A_BYTES);
    cudaFuncSetAttribute(k_gate<0>, cudaFuncAttributeMaxDynamicSharedMemorySize, SMEM_G_BYTES);
    cudaFuncSetAttribute(k_gate<1>, cudaFuncAttributeMaxDynamicSharedMemorySize, SMEM_G_BYTES);
    cudaFuncSetAttribute(k_gate<2>, cudaFuncAttributeMaxDynamicSharedMemorySize, SMEM_G_BYTES);

    const float* hps[4] = { hidden, h0, h1, h0 };
    float*       hns[4] = { h0, h1, h0, out };

    for (int s = 0; s < 4; s++) {
        const float* hp = hps[s];
        float*       hn = hns[s];
        k_mma_a<<<dim3(4, BQ), 256, SMEM_A_BYTES>>>(A, hp, b_ah, ga);
        k_gate<0><<<M2 / 128, 256, SMEM_G_BYTES>>>(ga, hp,  w_z, u_z, b_wz, b_uz, hp, nullptr, gz);
        k_gate<1><<<M2 / 128, 256, SMEM_G_BYTES>>>(ga, hp,  w_r, u_r, b_wr, b_ur, hp, nullptr, grh);
        k_gate<2><<<M2 / 128, 256, SMEM_G_BYTES>>>(ga, grh, w,   u,   b_w,  b_u,  hp, gz,     hn);
    }
}

// round 6
// speedup vs baseline: 1.4457x; 1.0574x over previous
#include <cuda_runtime.h>
#include <math.h>
#include <stdint.h>

#define BQ 128
#define NQ 512
#define HQ 128
#define M2 65536

// ---------------- scratch (allocation-free rule) ----------------
__device__ float g_Ahi[(size_t)BQ * NQ * NQ];
__device__ float g_Alo[(size_t)BQ * NQ * NQ];
__device__ float g_ahi[(size_t)M2 * HQ];
__device__ float g_alo[(size_t)M2 * HQ];
__device__ float g_rhhi[(size_t)M2 * HQ];
__device__ float g_rhlo[(size_t)M2 * HQ];
__device__ float g_z  [(size_t)M2 * HQ];
__device__ float g_h0 [(size_t)M2 * HQ];
__device__ float g_h1 [(size_t)M2 * HQ];
__device__ float g_h0hi[(size_t)M2 * HQ];
__device__ float g_h0lo[(size_t)M2 * HQ];
__device__ float g_h1hi[(size_t)M2 * HQ];
__device__ float g_h1lo[(size_t)M2 * HQ];
__device__ float g_Wsp[12 * (size_t)HQ * HQ];   // 6 weights x (hi,lo)

// ---------------- helpers ----------------
__device__ __forceinline__ void cpa16(uint32_t dst, const float* src) {
    asm volatile("cp.async.cg.shared.global [%0], [%1], 16;" :: "r"(dst), "l"(src));
}
#define CP_COMMIT() asm volatile("cp.async.commit_group;" ::: "memory")
#define CP_WAIT1()  asm volatile("cp.async.wait_group 1;" ::: "memory")
#define CP_WAIT0()  asm volatile("cp.async.wait_group 0;" ::: "memory")

__device__ __forceinline__ uint32_t smem_u32(const void* p) {
    uint32_t a;
    asm("{ .reg .u64 t; cvta.to.shared.u64 t, %1; cvt.u32.u64 %0, t; }" : "=r"(a) : "l"(p));
    return a;
}
__device__ __forceinline__ uint32_t f2tf(float x) {
    uint32_t r;
    asm("cvt.rna.tf32.f32 %0, %1;" : "=r"(r) : "f"(x));
    return r;
}
__device__ __forceinline__ void fsplit(float x, float& h, float& l) {
    h = __uint_as_float(f2tf(x));
    l = __uint_as_float(f2tf(x - h));
}
__device__ __forceinline__ void mma8(float* c, const uint32_t* a, const uint32_t* b) {
    asm volatile(
        "mma.sync.aligned.m16n8k8.row.col.f32.tf32.tf32.f32 "
        "{%0,%1,%2,%3}, {%4,%5,%6,%7}, {%8,%9}, {%0,%1,%2,%3};"
        : "+f"(c[0]), "+f"(c[1]), "+f"(c[2]), "+f"(c[3])
        : "r"(a[0]), "r"(a[1]), "r"(a[2]), "r"(a[3]), "r"(b[0]), "r"(b[1]));
}

// ---------------------------------------------------------------------------
// Split pre-pass: x -> (tf32 hi, tf32 lo), vectorized float4
// ---------------------------------------------------------------------------
__global__ __launch_bounds__(256)
void k_split(const float* __restrict__ s, float* __restrict__ hi,
             float* __restrict__ lo, int n4)
{
    int i = blockIdx.x * blockDim.x + threadIdx.x;
    if (i >= n4) return;
    float4 v = reinterpret_cast<const float4*>(s)[i];
    float4 h, l;
    fsplit(v.x, h.x, l.x); fsplit(v.y, h.y, l.y);
    fsplit(v.z, h.z, l.z); fsplit(v.w, h.w, l.w);
    reinterpret_cast<float4*>(hi)[i] = h;
    reinterpret_cast<float4*>(lo)[i] = l;
}

// ---------------------------------------------------------------------------
// a-GEMM: a[b,n,h] = sum_m A[b,m,n]*h[b,m,h] + bias[h]; writes a as hi/lo.
// K-major smem tiles [k][i], stride 136 words, K-chunk 16, C=32 chunks.
// smem per stage: 4 tiles x 16x136x4B = 34816; x2 stages = 69632 B.
// ---------------------------------------------------------------------------
#define AT_W 2176            // words per tile (16*136)
#define AS_W 8704            // words per stage (4 tiles)
__global__ __launch_bounds__(256, 2)
void k_mma_a(const float* __restrict__ Ahi, const float* __restrict__ Alo,
             const float* __restrict__ Hhi, const float* __restrict__ Hlo,
             const float* __restrict__ bias,
             float* __restrict__ ahi, float* __restrict__ alo)
{
    extern __shared__ uint32_t su[];
    const uint32_t sb = smem_u32(su);
    const int t = threadIdx.x, lane = t & 31, wid = t >> 5;
    const int wi = wid & 1, wj = wid >> 1;
    const int g = lane >> 2, tq = lane & 3;
    const int b = blockIdx.y, n0 = blockIdx.x * 128;

    const float* srcs[4] = {
        Ahi + (size_t)b * NQ * NQ + n0, Alo + (size_t)b * NQ * NQ + n0,
        Hhi + (size_t)b * NQ * HQ,      Hlo + (size_t)b * NQ * HQ };
    const int strides[4] = { NQ, NQ, HQ, HQ };

    float acc[4][4][4];
#pragma unroll
    for (int a_ = 0; a_ < 4; a_++)
#pragma unroll
        for (int b_ = 0; b_ < 4; b_++)
#pragma unroll
            for (int c_ = 0; c_ < 4; c_++) acc[a_][b_][c_] = 0.f;

    const int C = 32;
    // loader: 16 k-rows x 128 floats per tile; 512 f4 per tile, 2/thread
    const int lk = t >> 5;          // wait: need k,c4 per f4 idx
    // idx = t + p*256 ; k = idx>>5 (0..15), c4 = idx&31
#define A_LOAD(cc, stage)                                                      \
    {                                                                          \
        const uint32_t s0 = sb + (uint32_t)(stage) * AS_W * 4;                 \
        _Pragma("unroll")                                                      \
        for (int tl = 0; tl < 4; tl++) {                                       \
            _Pragma("unroll")                                                  \
            for (int p = 0; p < 2; p++) {                                      \
                const int idx = t + p * 256;                                   \
                const int k = idx >> 5, c4 = idx & 31;                         \
                cpa16(s0 + (uint32_t)(tl * AT_W + k * 136 + c4 * 4) * 4,       \
                      srcs[tl] + (size_t)((cc) * 16 + k) * strides[tl] + c4 * 4); \
            }                                                                  \
        }                                                                      \
        CP_COMMIT();                                                           \
    }

    A_LOAD(0, 0);
    for (int c = 0; c < C; c++) {
        if (c + 1 < C) { A_LOAD(c + 1, (c + 1) & 1); CP_WAIT1(); }
        else           { CP_WAIT0(); }
        __syncthreads();
        const uint32_t* Xh = su + (c & 1) * AS_W;
        const uint32_t* Xl = Xh + AT_W;
        const uint32_t* Wh = Xh + 2 * AT_W;
        const uint32_t* Wl = Xh + 3 * AT_W;
#pragma unroll
        for (int kb = 0; kb < 16; kb += 8) {
            uint32_t ah[4][4], al[4][4], bh[4][2], bl[4][2];
#pragma unroll
            for (int mf = 0; mf < 4; mf++) {
                const int r = wi * 64 + mf * 16 + g;
                ah[mf][0] = Xh[(kb + tq) * 136 + r];
                ah[mf][1] = Xh[(kb + tq) * 136 + r + 8];
                ah[mf][2] = Xh[(kb + tq + 4) * 136 + r];
                ah[mf][3] = Xh[(kb + tq + 4) * 136 + r + 8];
                al[mf][0] = Xl[(kb + tq) * 136 + r];
                al[mf][1] = Xl[(kb + tq) * 136 + r + 8];
                al[mf][2] = Xl[(kb + tq + 4) * 136 + r];
                al[mf][3] = Xl[(kb + tq + 4) * 136 + r + 8];
            }
#pragma unroll
            for (int nf = 0; nf < 4; nf++) {
                const int cj = wj * 32 + nf * 8 + g;
                bh[nf][0] = Wh[(kb + tq) * 136 + cj];
                bh[nf][1] = Wh[(kb + tq + 4) * 136 + cj];
                bl[nf][0] = Wl[(kb + tq) * 136 + cj];
                bl[nf][1] = Wl[(kb + tq + 4) * 136 + cj];
            }
#pragma unroll
            for (int mf = 0; mf < 4; mf++)
#pragma unroll
                for (int nf = 0; nf < 4; nf++) {
                    mma8(acc[mf][nf], al[mf], bh[nf]);
                    mma8(acc[mf][nf], ah[mf], bl[nf]);
                    mma8(acc[mf][nf], ah[mf], bh[nf]);
                }
        }
        __syncthreads();
    }
#undef A_LOAD

    const size_t obase = (size_t)b * NQ * HQ;
#pragma unroll
    for (int mf = 0; mf < 4; mf++) {
#pragma unroll
        for (int h2 = 0; h2 < 2; h2++) {
            const int i = n0 + wi * 64 + mf * 16 + g + h2 * 8;
            const size_t rb = obase + (size_t)i * HQ;
#pragma unroll
            for (int nf = 0; nf < 4; nf++) {
                const int j = wj * 32 + nf * 8 + 2 * tq;
                const float2 bb = *reinterpret_cast<const float2*>(bias + j);
                float v0 = acc[mf][nf][h2 * 2 + 0] + bb.x;
                float v1 = acc[mf][nf][h2 * 2 + 1] + bb.y;
                float2 vh, vl;
                fsplit(v0, vh.x, vl.x);
                fsplit(v1, vh.y, vl.y);
                *reinterpret_cast<float2*>(ahi + rb + j) = vh;
                *reinterpret_cast<float2*>(alo + rb + j) = vl;
            }
        }
    }
}

// ---------------------------------------------------------------------------
// Gate GEMM: D = X1 W1^T + X2 W2^T (+biases); fused GRU epilogue.
//   MODE 0: z = sigmoid(D)           -> raw
//   MODE 1: rh = sigmoid(D)*hp       -> hi/lo
//   MODE 2: h' = (1-z)hp + z tanh(D) -> raw + hi/lo
// M-major smem tiles [i][k], stride 20 words, K-chunk 16, C=16 chunks.
// smem per stage: 4 tiles x 128x20x4B = 40960; x2 stages = 81920 B.
// ---------------------------------------------------------------------------
#define GT_W 2560            // words per tile (128*20)
#define GS_W 10240           // words per stage
template<int MODE>
__global__ __launch_bounds__(256, 2)
void k_gate(const float* __restrict__ X1h, const float* __restrict__ X1l,
            const float* __restrict__ X2h, const float* __restrict__ X2l,
            const float* __restrict__ W1h, const float* __restrict__ W1l,
            const float* __restrict__ W2h, const float* __restrict__ W2l,
            const float* __restrict__ b1, const float* __restrict__ b2,
            const float* __restrict__ hp, const float* __restrict__ zp,
            float* __restrict__ outr, float* __restrict__ outhi,
            float* __restrict__ outlo)
{
    extern __shared__ uint32_t su[];
    const uint32_t sb = smem_u32(su);
    const int t = threadIdx.x, lane = t & 31, wid = t >> 5;
    const int wi = wid & 1, wj = wid >> 1;
    const int g = lane >> 2, tq = lane & 3;
    const int i0 = blockIdx.x * 128;

    const float* xh[2] = { X1h + (size_t)i0 * HQ, X2h + (size_t)i0 * HQ };
    const float* xl[2] = { X1l + (size_t)i0 * HQ, X2l + (size_t)i0 * HQ };
    const float* wh[2] = { W1h, W2h };
    const float* wl[2] = { W1l, W2l };

    float acc[4][4][4];
#pragma unroll
    for (int a_ = 0; a_ < 4; a_++)
#pragma unroll
        for (int b_ = 0; b_ < 4; b_++)
#pragma unroll
            for (int c_ = 0; c_ < 4; c_++) acc[a_][b_][c_] = 0.f;

    const int C = 16;
    // loader: 128 rows x 16 k per tile; 512 f4 per tile, 2/thread
#define G_LOAD(cc, stage)                                                      \
    {                                                                          \
        const int gg = (cc) >> 3;                                              \
        const int kc = ((cc) & 7) * 16;                                        \
        const uint32_t s0 = sb + (uint32_t)(stage) * GS_W * 4;                 \
        const float* srcs[4] = { xh[gg] + kc, xl[gg] + kc,                     \
                                 wh[gg] + kc, wl[gg] + kc };                   \
        _Pragma("unroll")                                                      \
        for (int tl = 0; tl < 4; tl++) {                                       \
            _Pragma("unroll")                                                  \
            for (int p = 0; p < 2; p++) {                                      \
                const int idx = t + p * 256;                                   \
                const int i = idx >> 2, f4 = idx & 3;                          \
                cpa16(s0 + (uint32_t)(tl * GT_W + i * 20 + f4 * 4) * 4,        \
                      srcs[tl] + (size_t)i * HQ + f4 * 4);                     \
            }                                                                  \
        }                                                                      \
        CP_COMMIT();                                                           \
    }

    G_LOAD(0, 0);
    for (int c = 0; c < C; c++) {
        if (c + 1 < C) { G_LOAD(c + 1, (c + 1) & 1); CP_WAIT1(); }
        else           { CP_WAIT0(); }
        __syncthreads();
        const uint32_t* Xh = su + (c & 1) * GS_W;
        const uint32_t* Xl = Xh + GT_W;
        const uint32_t* Wh = Xh + 2 * GT_W;
        const uint32_t* Wl = Xh + 3 * GT_W;
#pragma unroll
        for (int kb = 0; kb < 16; kb += 8) {
            uint32_t ah[4][4], al[4][4], bh[4][2], bl[4][2];
#pragma unroll
            for (int mf = 0; mf < 4; mf++) {
                const int r = wi * 64 + mf * 16 + g;
                ah[mf][0] = Xh[r * 20 + kb + tq];
                ah[mf][1] = Xh[(r + 8) * 20 + kb + tq];
                ah[mf][2] = Xh[r * 20 + kb + tq + 4];
                ah[mf][3] = Xh[(r + 8) * 20 + kb + tq + 4];
                al[mf][0] = Xl[r * 20 + kb + tq];
                al[mf][1] = Xl[(r + 8) * 20 + kb + tq];
                al[mf][2] = Xl[r * 20 + kb + tq + 4];
                al[mf][3] = Xl[(r + 8) * 20 + kb + tq + 4];
            }
#pragma unroll
            for (int nf = 0; nf < 4; nf++) {
                const int cj = wj * 32 + nf * 8 + g;
                bh[nf][0] = Wh[cj * 20 + kb + tq];
                bh[nf][1] = Wh[cj * 20 + kb + tq + 4];
                bl[nf][0] = Wl[cj * 20 + kb + tq];
                bl[nf][1] = Wl[cj * 20 + kb + tq + 4];
            }
#pragma unroll
            for (int mf = 0; mf < 4; mf++)
#pragma unroll
                for (int nf = 0; nf < 4; nf++) {
                    mma8(acc[mf][nf], al[mf], bh[nf]);
                    mma8(acc[mf][nf], ah[mf], bl[nf]);
                    mma8(acc[mf][nf], ah[mf], bh[nf]);
                }
        }
        __syncthreads();
    }
#undef G_LOAD

#pragma unroll
    for (int mf = 0; mf < 4; mf++) {
#pragma unroll
        for (int h2 = 0; h2 < 2; h2++) {
            const int i = i0 + wi * 64 + mf * 16 + g + h2 * 8;
            const size_t rb = (size_t)i * HQ;
#pragma unroll
            for (int nf = 0; nf < 4; nf++) {
                const int j = wj * 32 + nf * 8 + 2 * tq;
                const float2 bb1 = *reinterpret_cast<const float2*>(b1 + j);
                const float2 bb2 = *reinterpret_cast<const float2*>(b2 + j);
                float v0 = acc[mf][nf][h2 * 2 + 0] + bb1.x + bb2.x;
                float v1 = acc[mf][nf][h2 * 2 + 1] + bb1.y + bb2.y;
                float2 o;
                if (MODE == 0) {
                    o.x = 1.f / (1.f + __expf(-v0));
                    o.y = 1.f / (1.f + __expf(-v1));
                    *reinterpret_cast<float2*>(outr + rb + j) = o;
                } else if (MODE == 1) {
                    const float2 hv = *reinterpret_cast<const float2*>(hp + rb + j);
                    o.x = hv.x * (1.f / (1.f + __expf(-v0)));
                    o.y = hv.y * (1.f / (1.f + __expf(-v1)));
                    float2 oh, ol;
                    fsplit(o.x, oh.x, ol.x); fsplit(o.y, oh.y, ol.y);
                    *reinterpret_cast<float2*>(outhi + rb + j) = oh;
                    *reinterpret_cast<float2*>(outlo + rb + j) = ol;
                } else {
                    const float2 hv = *reinterpret_cast<const float2*>(hp + rb + j);
                    const float2 zz = *reinterpret_cast<const float2*>(zp + rb + j);
                    o.x = (1.f - zz.x) * hv.x + zz.x * tanhf(v0);
                    o.y = (1.f - zz.y) * hv.y + zz.y * tanhf(v1);
                    *reinterpret_cast<float2*>(outr + rb + j) = o;
                    float2 oh, ol;
                    fsplit(o.x, oh.x, ol.x); fsplit(o.y, oh.y, ol.y);
                    *reinterpret_cast<float2*>(outhi + rb + j) = oh;
                    *reinterpret_cast<float2*>(outlo + rb + j) = ol;
                }
            }
        }
    }
}

// ---------------------------------------------------------------------------
// Host launcher
// ---------------------------------------------------------------------------
extern "C" void kernel_launch(void* const* d_in, const int* in_sizes, int n_in,
                              void* d_out, int out_size)
{
    const float* A      = (const float*)d_in[0];
    const float* hidden = (const float*)d_in[1];
    const float* b_ah   = (const float*)d_in[2];
    const float* w_z    = (const float*)d_in[3];
    const float* b_wz   = (const float*)d_in[4];
    const float* u_z    = (const float*)d_in[5];
    const float* b_uz   = (const float*)d_in[6];
    const float* w_r    = (const float*)d_in[7];
    const float* b_wr   = (const float*)d_in[8];
    const float* u_r    = (const float*)d_in[9];
    const float* b_ur   = (const float*)d_in[10];
    const float* w      = (const float*)d_in[11];
    const float* b_w    = (const float*)d_in[12];
    const float* u      = (const float*)d_in[13];
    const float* b_u    = (const float*)d_in[14];
    float* out = (float*)d_out;

    float *Ahi, *Alo, *ahi, *alo, *rhhi, *rhlo, *zr, *h0, *h1;
    float *h0hi, *h0lo, *h1hi, *h1lo, *Wsp;
    cudaGetSymbolAddress((void**)&Ahi,  g_Ahi);
    cudaGetSymbolAddress((void**)&Alo,  g_Alo);
    cudaGetSymbolAddress((void**)&ahi,  g_ahi);
    cudaGetSymbolAddress((void**)&alo,  g_alo);
    cudaGetSymbolAddress((void**)&rhhi, g_rhhi);
    cudaGetSymbolAddress((void**)&rhlo, g_rhlo);
    cudaGetSymbolAddress((void**)&zr,   g_z);
    cudaGetSymbolAddress((void**)&h0,   g_h0);
    cudaGetSymbolAddress((void**)&h1,   g_h1);
    cudaGetSymbolAddress((void**)&h0hi, g_h0hi);
    cudaGetSymbolAddress((void**)&h0lo, g_h0lo);
    cudaGetSymbolAddress((void**)&h1hi, g_h1hi);
    cudaGetSymbolAddress((void**)&h1lo, g_h1lo);
    cudaGetSymbolAddress((void**)&Wsp,  g_Wsp);

    cudaFuncSetAttribute(k_mma_a,   cudaFuncAttributeMaxDynamicSharedMemorySize, 69632);
    cudaFuncSetAttribute(k_gate<0>, cudaFuncAttributeMaxDynamicSharedMemorySize, 81920);
    cudaFuncSetAttribute(k_gate<1>, cudaFuncAttributeMaxDynamicSharedMemorySize, 81920);
    cudaFuncSetAttribute(k_gate<2>, cudaFuncAttributeMaxDynamicSharedMemorySize, 81920);

    const int S = HQ * HQ;   // 16384
    // Weight splits: [0,1]=wz, [2,3]=uz, [4,5]=wr, [6,7]=ur, [8,9]=w, [10,11]=u
    k_split<<<S / 1024, 256>>>(w_z, Wsp + 0 * S,  Wsp + 1 * S,  S / 4);
    k_split<<<S / 1024, 256>>>(u_z, Wsp + 2 * S,  Wsp + 3 * S,  S / 4);
    k_split<<<S / 1024, 256>>>(w_r, Wsp + 4 * S,  Wsp + 5 * S,  S / 4);
    k_split<<<S / 1024, 256>>>(u_r, Wsp + 6 * S,  Wsp + 7 * S,  S / 4);
    k_split<<<S / 1024, 256>>>(w,   Wsp + 8 * S,  Wsp + 9 * S,  S / 4);
    k_split<<<S / 1024, 256>>>(u,   Wsp + 10 * S, Wsp + 11 * S, S / 4);
    // A split (once per launch)
    k_split<<<(BQ * NQ * NQ / 4 + 255) / 256, 256>>>(A, Ahi, Alo, BQ * NQ * NQ / 4);
    // initial hidden split -> h1hi/h1lo (consumed at step 0, overwritten at step 1)
    k_split<<<(M2 * HQ / 4 + 255) / 256, 256>>>(hidden, h1hi, h1lo, M2 * HQ / 4);

    const float* hpr[4]  = { hidden, h0, h1, h0 };
    const float* hph[4]  = { h1hi, h0hi, h1hi, h0hi };
    const float* hpl[4]  = { h1lo, h0lo, h1lo, h0lo };
    float*       hnr[4]  = { h0, h1, h0, out };
    float*       hnh[4]  = { h0hi, h1hi, h0hi, h1hi };
    float*       hnl[4]  = { h0lo, h1lo, h0lo, h1lo };

    for (int s = 0; s < 4; s++) {
        k_mma_a<<<dim3(4, BQ), 256, 69632>>>(Ahi, Alo, hph[s], hpl[s], b_ah, ahi, alo);
        k_gate<0><<<M2 / 128, 256, 81920>>>(
            ahi, alo, hph[s], hpl[s],
            Wsp + 0 * S, Wsp + 1 * S, Wsp + 2 * S, Wsp + 3 * S,
            b_wz, b_uz, hpr[s], nullptr, zr, nullptr, nullptr);
        k_gate<1><<<M2 / 128, 256, 81920>>>(
            ahi, alo, hph[s], hpl[s],
            Wsp + 4 * S, Wsp + 5 * S, Wsp + 6 * S, Wsp + 7 * S,
            b_wr, b_ur, hpr[s], nullptr, nullptr, rhhi, rhlo);
        k_gate<2><<<M2 / 128, 256, 81920>>>(
            ahi, alo, rhhi, rhlo,
            Wsp + 8 * S, Wsp + 9 * S, Wsp + 10 * S, Wsp + 11 * S,
            b_w, b_u, hpr[s], zr, hnr[s], hnh[s], hnl[s]);
    }
}

// round 7
// speedup vs baseline: 1.4683x; 1.0157x over previous
#include <cuda_runtime.h>
#include <math.h>
#include <stdint.h>

#define BQ 128
#define NQ 512
#define HQ 128
#define M2 65536

// ---------------- scratch (allocation-free rule) ----------------
__device__ float g_Ahi[(size_t)BQ * NQ * NQ];
__device__ float g_Alo[(size_t)BQ * NQ * NQ];
__device__ float g_ahi[(size_t)M2 * HQ];
__device__ float g_alo[(size_t)M2 * HQ];
__device__ float g_rhhi[(size_t)M2 * HQ];
__device__ float g_rhlo[(size_t)M2 * HQ];
__device__ float g_z  [(size_t)M2 * HQ];
__device__ float g_h0 [(size_t)M2 * HQ];
__device__ float g_h1 [(size_t)M2 * HQ];
__device__ float g_h0hi[(size_t)M2 * HQ];
__device__ float g_h0lo[(size_t)M2 * HQ];
__device__ float g_h1hi[(size_t)M2 * HQ];
__device__ float g_h1lo[(size_t)M2 * HQ];
__device__ float g_Wsp[12 * (size_t)HQ * HQ];   // [0,1]=wz [2,3]=uz [4,5]=wr [6,7]=ur [8,9]=w [10,11]=u (hi,lo)

// ---------------- helpers ----------------
__device__ __forceinline__ void cpa16(uint32_t dst, const float* src) {
    asm volatile("cp.async.cg.shared.global [%0], [%1], 16;" :: "r"(dst), "l"(src));
}
#define CP_COMMIT() asm volatile("cp.async.commit_group;" ::: "memory")
#define CP_WAIT2()  asm volatile("cp.async.wait_group 2;" ::: "memory")
#define CP_WAIT1()  asm volatile("cp.async.wait_group 1;" ::: "memory")
#define CP_WAIT0()  asm volatile("cp.async.wait_group 0;" ::: "memory")

__device__ __forceinline__ uint32_t smem_u32(const void* p) {
    uint32_t a;
    asm("{ .reg .u64 t; cvta.to.shared.u64 t, %1; cvt.u32.u64 %0, t; }" : "=r"(a) : "l"(p));
    return a;
}
__device__ __forceinline__ uint32_t f2tf(float x) {
    uint32_t r;
    asm("cvt.rna.tf32.f32 %0, %1;" : "=r"(r) : "f"(x));
    return r;
}
__device__ __forceinline__ void fsplit(float x, float& h, float& l) {
    h = __uint_as_float(f2tf(x));
    l = __uint_as_float(f2tf(x - h));
}
__device__ __forceinline__ void mma8(float* c, const uint32_t* a, const uint32_t* b) {
    asm volatile(
        "mma.sync.aligned.m16n8k8.row.col.f32.tf32.tf32.f32 "
        "{%0,%1,%2,%3}, {%4,%5,%6,%7}, {%8,%9}, {%0,%1,%2,%3};"
        : "+f"(c[0]), "+f"(c[1]), "+f"(c[2]), "+f"(c[3])
        : "r"(a[0]), "r"(a[1]), "r"(a[2]), "r"(a[3]), "r"(b[0]), "r"(b[1]));
}

// ---------------------------------------------------------------------------
// Split pre-pass: x -> (tf32 hi, tf32 lo), vectorized float4
// ---------------------------------------------------------------------------
__global__ __launch_bounds__(256)
void k_split(const float* __restrict__ s, float* __restrict__ hi,
             float* __restrict__ lo, int n4)
{
    int i = blockIdx.x * blockDim.x + threadIdx.x;
    if (i >= n4) return;
    float4 v = reinterpret_cast<const float4*>(s)[i];
    float4 h, l;
    fsplit(v.x, h.x, l.x); fsplit(v.y, h.y, l.y);
    fsplit(v.z, h.z, l.z); fsplit(v.w, h.w, l.w);
    reinterpret_cast<float4*>(hi)[i] = h;
    reinterpret_cast<float4*>(lo)[i] = l;
}

// ---------------------------------------------------------------------------
// a-GEMM: a[b,n,h] = sum_m A[b,m,n]*h[b,m,h] + bias[h]; writes a hi/lo.
// K-major smem [k][i], stride 136 w. K-chunk 16, C=32. 3-stage cp.async.
// smem = 3 * 34816 = 104448 B. 2 CTA/SM.
// ---------------------------------------------------------------------------
#define AT_W 2176            // words per tile (16*136)
#define AS_W 8704            // words per stage (4 tiles)
__global__ __launch_bounds__(256, 2)
void k_mma_a(const float* __restrict__ Ahi, const float* __restrict__ Alo,
             const float* __restrict__ Hhi, const float* __restrict__ Hlo,
             const float* __restrict__ bias,
             float* __restrict__ ahi, float* __restrict__ alo)
{
    extern __shared__ uint32_t su[];
    const uint32_t sb = smem_u32(su);
    const int t = threadIdx.x, lane = t & 31, wid = t >> 5;
    const int wi = wid & 1, wj = wid >> 1;
    const int g = lane >> 2, tq = lane & 3;
    const int b = blockIdx.y, n0 = blockIdx.x * 128;

    const float* s0p = Ahi + (size_t)b * NQ * NQ + n0;
    const float* s1p = Alo + (size_t)b * NQ * NQ + n0;
    const float* s2p = Hhi + (size_t)b * NQ * HQ;
    const float* s3p = Hlo + (size_t)b * NQ * HQ;

    float acc[4][4][4];
#pragma unroll
    for (int a_ = 0; a_ < 4; a_++)
#pragma unroll
        for (int b_ = 0; b_ < 4; b_++)
#pragma unroll
            for (int c_ = 0; c_ < 4; c_++) acc[a_][b_][c_] = 0.f;

    const int C = 32;
#define A_LOAD(cc, st)                                                         \
    {                                                                          \
        const uint32_t s0 = sb + (uint32_t)(st) * AS_W * 4;                    \
        _Pragma("unroll")                                                      \
        for (int p = 0; p < 2; p++) {                                          \
            const int idx = t + p * 256;                                       \
            const int k = idx >> 5, c4 = idx & 31;                             \
            const uint32_t off = (uint32_t)(k * 136 + c4 * 4) * 4;             \
            const int row = (cc) * 16 + k;                                     \
            cpa16(s0 + off,                 s0p + (size_t)row * NQ + c4 * 4);  \
            cpa16(s0 + AT_W * 4 + off,     s1p + (size_t)row * NQ + c4 * 4);  \
            cpa16(s0 + 2 * AT_W * 4 + off, s2p + (size_t)row * HQ + c4 * 4);  \
            cpa16(s0 + 3 * AT_W * 4 + off, s3p + (size_t)row * HQ + c4 * 4);  \
        }                                                                      \
        CP_COMMIT();                                                           \
    }

    A_LOAD(0, 0);
    A_LOAD(1, 1);
    int st2 = 2;
    for (int c = 0; c < C; c++) {
        if (c + 2 < C) {
            A_LOAD(c + 2, st2);
            st2 = (st2 == 2) ? 0 : st2 + 1;
            CP_WAIT2();
        } else if (c + 1 < C) {
            CP_WAIT1();
        } else {
            CP_WAIT0();
        }
        __syncthreads();
        const int cs = c % 3;
        const uint32_t* Xh = su + cs * AS_W;
        const uint32_t* Xl = Xh + AT_W;
        const uint32_t* Wh = Xh + 2 * AT_W;
        const uint32_t* Wl = Xh + 3 * AT_W;
#pragma unroll
        for (int kb = 0; kb < 16; kb += 8) {
            uint32_t ah[4][4], al[4][4];
#pragma unroll
            for (int mf = 0; mf < 4; mf++) {
                const int r = wi * 64 + mf * 16 + g;
                ah[mf][0] = Xh[(kb + tq) * 136 + r];
                ah[mf][1] = Xh[(kb + tq) * 136 + r + 8];
                ah[mf][2] = Xh[(kb + tq + 4) * 136 + r];
                ah[mf][3] = Xh[(kb + tq + 4) * 136 + r + 8];
                al[mf][0] = Xl[(kb + tq) * 136 + r];
                al[mf][1] = Xl[(kb + tq) * 136 + r + 8];
                al[mf][2] = Xl[(kb + tq + 4) * 136 + r];
                al[mf][3] = Xl[(kb + tq + 4) * 136 + r + 8];
            }
#pragma unroll
            for (int nf = 0; nf < 4; nf++) {
                const int cj = wj * 32 + nf * 8 + g;
                uint32_t bh[2], bl[2];
                bh[0] = Wh[(kb + tq) * 136 + cj];
                bh[1] = Wh[(kb + tq + 4) * 136 + cj];
                bl[0] = Wl[(kb + tq) * 136 + cj];
                bl[1] = Wl[(kb + tq + 4) * 136 + cj];
#pragma unroll
                for (int mf = 0; mf < 4; mf++) {
                    mma8(acc[mf][nf], al[mf], bh);
                    mma8(acc[mf][nf], ah[mf], bl);
                    mma8(acc[mf][nf], ah[mf], bh);
                }
            }
        }
        __syncthreads();
    }
#undef A_LOAD

    const size_t obase = (size_t)b * NQ * HQ;
#pragma unroll
    for (int mf = 0; mf < 4; mf++) {
#pragma unroll
        for (int h2 = 0; h2 < 2; h2++) {
            const int i = n0 + wi * 64 + mf * 16 + g + h2 * 8;
            const size_t rb = obase + (size_t)i * HQ;
#pragma unroll
            for (int nf = 0; nf < 4; nf++) {
                const int j = wj * 32 + nf * 8 + 2 * tq;
                const float2 bb = *reinterpret_cast<const float2*>(bias + j);
                float v0 = acc[mf][nf][h2 * 2 + 0] + bb.x;
                float v1 = acc[mf][nf][h2 * 2 + 1] + bb.y;
                float2 vh, vl;
                fsplit(v0, vh.x, vl.x);
                fsplit(v1, vh.y, vl.y);
                *reinterpret_cast<float2*>(ahi + rb + j) = vh;
                *reinterpret_cast<float2*>(alo + rb + j) = vl;
            }
        }
    }
}

// ---------------------------------------------------------------------------
// Fused z+r: N=256 concat GEMM: [z|r] = a@[wz|wr]^T + h@[uz|ur]^T (+biases)
//   cols 0..127  -> z = sigmoid(.)          -> zout (raw)
//   cols 128..255-> r = sigmoid(.); rh=r*h  -> rhhi/rhlo
// CTA tile 64 rows x 256 cols, 256 thr (8 warps, warp = 64x32), K-chunk 16.
// M-major smem [i][k] / [j][k], stride 20 w. 2-stage. smem 102400 B. 2 CTA/SM.
// ---------------------------------------------------------------------------
#define ZT_X 1280            // X tile words (64*20)
#define ZT_W 5120            // W tile words (256*20)
#define ZS_W 12800           // stage words
__global__ __launch_bounds__(256, 2)
void k_zr(const float* __restrict__ ahi, const float* __restrict__ alo,
          const float* __restrict__ hhi, const float* __restrict__ hlo,
          const float* __restrict__ Wsp,
          const float* __restrict__ b_wz, const float* __restrict__ b_uz,
          const float* __restrict__ b_wr, const float* __restrict__ b_ur,
          const float* __restrict__ hraw,
          float* __restrict__ zout, float* __restrict__ rhhi,
          float* __restrict__ rhlo)
{
    extern __shared__ uint32_t su[];
    const uint32_t sb = smem_u32(su);
    const int t = threadIdx.x, lane = t & 31, wj = t >> 5;
    const int g = lane >> 2, tq = lane & 3;
    const int i0 = blockIdx.x * 64;
    const int S = HQ * HQ;

    float acc[4][4][4];
#pragma unroll
    for (int a_ = 0; a_ < 4; a_++)
#pragma unroll
        for (int b_ = 0; b_ < 4; b_++)
#pragma unroll
            for (int c_ = 0; c_ < 4; c_++) acc[a_][b_][c_] = 0.f;

    const int C = 16;
#define Z_LOAD(cc, st)                                                         \
    {                                                                          \
        const int half = (cc) >> 3;                                            \
        const int kc = ((cc) & 7) * 16;                                        \
        const float* xh_ = (half ? hhi : ahi) + (size_t)i0 * HQ + kc;          \
        const float* xl_ = (half ? hlo : alo) + (size_t)i0 * HQ + kc;          \
        const float* w1h = Wsp + (half ? 2 : 0) * S + kc;                      \
        const float* w1l = Wsp + (half ? 3 : 1) * S + kc;                      \
        const float* w2h = Wsp + (half ? 6 : 4) * S + kc;                      \
        const float* w2l = Wsp + (half ? 7 : 5) * S + kc;                      \
        const uint32_t s0 = sb + (uint32_t)(st) * ZS_W * 4;                    \
        {                                                                      \
            const int row = t >> 2, f4 = t & 3;                                \
            const uint32_t off = (uint32_t)(row * 20 + f4 * 4) * 4;            \
            cpa16(s0 + off,            xh_ + (size_t)row * HQ + f4 * 4);       \
            cpa16(s0 + ZT_X * 4 + off, xl_ + (size_t)row * HQ + f4 * 4);       \
        }                                                                      \
        _Pragma("unroll")                                                      \
        for (int p = 0; p < 4; p++) {                                          \
            const int idx = t + p * 256;                                       \
            const int row = idx >> 2, f4 = idx & 3;                            \
            const uint32_t off = (uint32_t)(row * 20 + f4 * 4) * 4;            \
            const float* sh = (row < 128) ? (w1h + (size_t)row * HQ)           \
                                          : (w2h + (size_t)(row - 128) * HQ);  \
            const float* sl = (row < 128) ? (w1l + (size_t)row * HQ)           \
                                          : (w2l + (size_t)(row - 128) * HQ);  \
            cpa16(s0 + 2 * ZT_X * 4 + off,            sh + f4 * 4);            \
            cpa16(s0 + (2 * ZT_X + ZT_W) * 4 + off,   sl + f4 * 4);            \
        }                                                                      \
        CP_COMMIT();                                                           \
    }

    Z_LOAD(0, 0);
    for (int c = 0; c < C; c++) {
        if (c + 1 < C) { Z_LOAD(c + 1, (c + 1) & 1); CP_WAIT1(); }
        else           { CP_WAIT0(); }
        __syncthreads();
        const uint32_t* Xh = su + (c & 1) * ZS_W;
        const uint32_t* Xl = Xh + ZT_X;
        const uint32_t* Wh = Xh + 2 * ZT_X;
        const uint32_t* Wl = Wh + ZT_W;
#pragma unroll
        for (int kb = 0; kb < 16; kb += 8) {
            uint32_t ah[4][4], al[4][4];
#pragma unroll
            for (int mf = 0; mf < 4; mf++) {
                const int r = mf * 16 + g;
                ah[mf][0] = Xh[r * 20 + kb + tq];
                ah[mf][1] = Xh[(r + 8) * 20 + kb + tq];
                ah[mf][2] = Xh[r * 20 + kb + tq + 4];
                ah[mf][3] = Xh[(r + 8) * 20 + kb + tq + 4];
                al[mf][0] = Xl[r * 20 + kb + tq];
                al[mf][1] = Xl[(r + 8) * 20 + kb + tq];
                al[mf][2] = Xl[r * 20 + kb + tq + 4];
                al[mf][3] = Xl[(r + 8) * 20 + kb + tq + 4];
            }
#pragma unroll
            for (int nf = 0; nf < 4; nf++) {
                const int cj = wj * 32 + nf * 8 + g;
                uint32_t bh[2], bl[2];
                bh[0] = Wh[cj * 20 + kb + tq];
                bh[1] = Wh[cj * 20 + kb + tq + 4];
                bl[0] = Wl[cj * 20 + kb + tq];
                bl[1] = Wl[cj * 20 + kb + tq + 4];
#pragma unroll
                for (int mf = 0; mf < 4; mf++) {
                    mma8(acc[mf][nf], al[mf], bh);
                    mma8(acc[mf][nf], ah[mf], bl);
                    mma8(acc[mf][nf], ah[mf], bh);
                }
            }
        }
        __syncthreads();
    }
#undef Z_LOAD

#pragma unroll
    for (int mf = 0; mf < 4; mf++) {
#pragma unroll
        for (int h2 = 0; h2 < 2; h2++) {
            const int i = i0 + mf * 16 + g + h2 * 8;
            const size_t rb = (size_t)i * HQ;
#pragma unroll
            for (int nf = 0; nf < 4; nf++) {
                const int j = wj * 32 + nf * 8 + 2 * tq;
                if (wj < 4) {
                    const float2 bb1 = *reinterpret_cast<const float2*>(b_wz + j);
                    const float2 bb2 = *reinterpret_cast<const float2*>(b_uz + j);
                    float v0 = acc[mf][nf][h2 * 2 + 0] + bb1.x + bb2.x;
                    float v1 = acc[mf][nf][h2 * 2 + 1] + bb1.y + bb2.y;
                    float2 o;
                    o.x = 1.f / (1.f + __expf(-v0));
                    o.y = 1.f / (1.f + __expf(-v1));
                    *reinterpret_cast<float2*>(zout + rb + j) = o;
                } else {
                    const int jj = j - 128;
                    const float2 bb1 = *reinterpret_cast<const float2*>(b_wr + jj);
                    const float2 bb2 = *reinterpret_cast<const float2*>(b_ur + jj);
                    float v0 = acc[mf][nf][h2 * 2 + 0] + bb1.x + bb2.x;
                    float v1 = acc[mf][nf][h2 * 2 + 1] + bb1.y + bb2.y;
                    const float2 hv = *reinterpret_cast<const float2*>(hraw + rb + jj);
                    float r0 = hv.x * (1.f / (1.f + __expf(-v0)));
                    float r1 = hv.y * (1.f / (1.f + __expf(-v1)));
                    float2 oh, ol;
                    fsplit(r0, oh.x, ol.x);
                    fsplit(r1, oh.y, ol.y);
                    *reinterpret_cast<float2*>(rhhi + rb + jj) = oh;
                    *reinterpret_cast<float2*>(rhlo + rb + jj) = ol;
                }
            }
        }
    }
}

// ---------------------------------------------------------------------------
// c-gate: D = a@w^T + rh@u^T (+b); h' = (1-z)h + z tanh(D); writes raw+hi/lo.
// CTA 128x128, K-chunk 16, C=16, 2-stage, stride 20 w. smem 81920 B. 2 CTA/SM.
// ---------------------------------------------------------------------------
#define GT_W 2560
#define GS_W 10240
__global__ __launch_bounds__(256, 2)
void k_cgate(const float* __restrict__ X1h, const float* __restrict__ X1l,
             const float* __restrict__ X2h, const float* __restrict__ X2l,
             const float* __restrict__ Wsp,
             const float* __restrict__ b1, const float* __restrict__ b2,
             const float* __restrict__ hp, const float* __restrict__ zp,
             float* __restrict__ outr, float* __restrict__ outhi,
             float* __restrict__ outlo)
{
    extern __shared__ uint32_t su[];
    const uint32_t sb = smem_u32(su);
    const int t = threadIdx.x, lane = t & 31, wid = t >> 5;
    const int wi = wid & 1, wj = wid >> 1;
    const int g = lane >> 2, tq = lane & 3;
    const int i0 = blockIdx.x * 128;
    const int S = HQ * HQ;

    float acc[4][4][4];
#pragma unroll
    for (int a_ = 0; a_ < 4; a_++)
#pragma unroll
        for (int b_ = 0; b_ < 4; b_++)
#pragma unroll
            for (int c_ = 0; c_ < 4; c_++) acc[a_][b_][c_] = 0.f;

    const int C = 16;
#define G_LOAD(cc, st)                                                         \
    {                                                                          \
        const int gg = (cc) >> 3;                                              \
        const int kc = ((cc) & 7) * 16;                                        \
        const float* xh_ = (gg ? X2h : X1h) + (size_t)i0 * HQ + kc;            \
        const float* xl_ = (gg ? X2l : X1l) + (size_t)i0 * HQ + kc;            \
        const float* wh_ = Wsp + (gg ? 10 : 8) * S + kc;                       \
        const float* wl_ = Wsp + (gg ? 11 : 9) * S + kc;                       \
        const uint32_t s0 = sb + (uint32_t)(st) * GS_W * 4;                    \
        _Pragma("unroll")                                                      \
        for (int p = 0; p < 2; p++) {                                          \
            const int idx = t + p * 256;                                       \
            const int row = idx >> 2, f4 = idx & 3;                            \
            const uint32_t off = (uint32_t)(row * 20 + f4 * 4) * 4;            \
            cpa16(s0 + off,                 xh_ + (size_t)row * HQ + f4 * 4);  \
            cpa16(s0 + GT_W * 4 + off,     xl_ + (size_t)row * HQ + f4 * 4);  \
            cpa16(s0 + 2 * GT_W * 4 + off, wh_ + (size_t)row * HQ + f4 * 4);  \
            cpa16(s0 + 3 * GT_W * 4 + off, wl_ + (size_t)row * HQ + f4 * 4);  \
        }                                                                      \
        CP_COMMIT();                                                           \
    }

    G_LOAD(0, 0);
    for (int c = 0; c < C; c++) {
        if (c + 1 < C) { G_LOAD(c + 1, (c + 1) & 1); CP_WAIT1(); }
        else           { CP_WAIT0(); }
        __syncthreads();
        const uint32_t* Xh = su + (c & 1) * GS_W;
        const uint32_t* Xl = Xh + GT_W;
        const uint32_t* Wh = Xh + 2 * GT_W;
        const uint32_t* Wl = Xh + 3 * GT_W;
#pragma unroll
        for (int kb = 0; kb < 16; kb += 8) {
            uint32_t ah[4][4], al[4][4];
#pragma unroll
            for (int mf = 0; mf < 4; mf++) {
                const int r = wi * 64 + mf * 16 + g;
                ah[mf][0] = Xh[r * 20 + kb + tq];
                ah[mf][1] = Xh[(r + 8) * 20 + kb + tq];
                ah[mf][2] = Xh[r * 20 + kb + tq + 4];
                ah[mf][3] = Xh[(r + 8) * 20 + kb + tq + 4];
                al[mf][0] = Xl[r * 20 + kb + tq];
                al[mf][1] = Xl[(r + 8) * 20 + kb + tq];
                al[mf][2] = Xl[r * 20 + kb + tq + 4];
                al[mf][3] = Xl[(r + 8) * 20 + kb + tq + 4];
            }
#pragma unroll
            for (int nf = 0; nf < 4; nf++) {
                const int cj = wj * 32 + nf * 8 + g;
                uint32_t bh[2], bl[2];
                bh[0] = Wh[cj * 20 + kb + tq];
                bh[1] = Wh[cj * 20 + kb + tq + 4];
                bl[0] = Wl[cj * 20 + kb + tq];
                bl[1] = Wl[cj * 20 + kb + tq + 4];
#pragma unroll
                for (int mf = 0; mf < 4; mf++) {
                    mma8(acc[mf][nf], al[mf], bh);
                    mma8(acc[mf][nf], ah[mf], bl);
                    mma8(acc[mf][nf], ah[mf], bh);
                }
            }
        }
        __syncthreads();
    }
#undef G_LOAD

#pragma unroll
    for (int mf = 0; mf < 4; mf++) {
#pragma unroll
        for (int h2 = 0; h2 < 2; h2++) {
            const int i = i0 + wi * 64 + mf * 16 + g + h2 * 8;
            const size_t rb = (size_t)i * HQ;
#pragma unroll
            for (int nf = 0; nf < 4; nf++) {
                const int j = wj * 32 + nf * 8 + 2 * tq;
                const float2 bb1 = *reinterpret_cast<const float2*>(b1 + j);
                const float2 bb2 = *reinterpret_cast<const float2*>(b2 + j);
                float v0 = acc[mf][nf][h2 * 2 + 0] + bb1.x + bb2.x;
                float v1 = acc[mf][nf][h2 * 2 + 1] + bb1.y + bb2.y;
                const float2 hv = *reinterpret_cast<const float2*>(hp + rb + j);
                const float2 zz = *reinterpret_cast<const float2*>(zp + rb + j);
                float2 o;
                o.x = (1.f - zz.x) * hv.x + zz.x * tanhf(v0);
                o.y = (1.f - zz.y) * hv.y + zz.y * tanhf(v1);
                *reinterpret_cast<float2*>(outr + rb + j) = o;
                float2 oh, ol;
                fsplit(o.x, oh.x, ol.x);
                fsplit(o.y, oh.y, ol.y);
                *reinterpret_cast<float2*>(outhi + rb + j) = oh;
                *reinterpret_cast<float2*>(outlo + rb + j) = ol;
            }
        }
    }
}

// ---------------------------------------------------------------------------
// Host launcher
// ---------------------------------------------------------------------------
extern "C" void kernel_launch(void* const* d_in, const int* in_sizes, int n_in,
                              void* d_out, int out_size)
{
    const float* A      = (const float*)d_in[0];
    const float* hidden = (const float*)d_in[1];
    const float* b_ah   = (const float*)d_in[2];
    const float* w_z    = (const float*)d_in[3];
    const float* b_wz   = (const float*)d_in[4];
    const float* u_z    = (const float*)d_in[5];
    const float* b_uz   = (const float*)d_in[6];
    const float* w_r    = (const float*)d_in[7];
    const float* b_wr   = (const float*)d_in[8];
    const float* u_r    = (const float*)d_in[9];
    const float* b_ur   = (const float*)d_in[10];
    const float* w      = (const float*)d_in[11];
    const float* b_w    = (const float*)d_in[12];
    const float* u      = (const float*)d_in[13];
    const float* b_u    = (const float*)d_in[14];
    float* out = (float*)d_out;

    float *Ahi, *Alo, *ahi, *alo, *rhhi, *rhlo, *zr, *h0, *h1;
    float *h0hi, *h0lo, *h1hi, *h1lo, *Wsp;
    cudaGetSymbolAddress((void**)&Ahi,  g_Ahi);
    cudaGetSymbolAddress((void**)&Alo,  g_Alo);
    cudaGetSymbolAddress((void**)&ahi,  g_ahi);
    cudaGetSymbolAddress((void**)&alo,  g_alo);
    cudaGetSymbolAddress((void**)&rhhi, g_rhhi);
    cudaGetSymbolAddress((void**)&rhlo, g_rhlo);
    cudaGetSymbolAddress((void**)&zr,   g_z);
    cudaGetSymbolAddress((void**)&h0,   g_h0);
    cudaGetSymbolAddress((void**)&h1,   g_h1);
    cudaGetSymbolAddress((void**)&h0hi, g_h0hi);
    cudaGetSymbolAddress((void**)&h0lo, g_h0lo);
    cudaGetSymbolAddress((void**)&h1hi, g_h1hi);
    cudaGetSymbolAddress((void**)&h1lo, g_h1lo);
    cudaGetSymbolAddress((void**)&Wsp,  g_Wsp);

    cudaFuncSetAttribute(k_mma_a, cudaFuncAttributeMaxDynamicSharedMemorySize, 104448);
    cudaFuncSetAttribute(k_zr,    cudaFuncAttributeMaxDynamicSharedMemorySize, 102400);
    cudaFuncSetAttribute(k_cgate, cudaFuncAttributeMaxDynamicSharedMemorySize, 81920);

    const int S = HQ * HQ;   // 16384
    k_split<<<S / 1024, 256>>>(w_z, Wsp + 0 * S,  Wsp + 1 * S,  S / 4);
    k_split<<<S / 1024, 256>>>(u_z, Wsp + 2 * S,  Wsp + 3 * S,  S / 4);
    k_split<<<S / 1024, 256>>>(w_r, Wsp + 4 * S,  Wsp + 5 * S,  S / 4);
    k_split<<<S / 1024, 256>>>(u_r, Wsp + 6 * S,  Wsp + 7 * S,  S / 4);
    k_split<<<S / 1024, 256>>>(w,   Wsp + 8 * S,  Wsp + 9 * S,  S / 4);
    k_split<<<S / 1024, 256>>>(u,   Wsp + 10 * S, Wsp + 11 * S, S / 4);
    k_split<<<(BQ * NQ * NQ / 4 + 255) / 256, 256>>>(A, Ahi, Alo, BQ * NQ * NQ / 4);
    k_split<<<(M2 * HQ / 4 + 255) / 256, 256>>>(hidden, h1hi, h1lo, M2 * HQ / 4);

    const float* hpr[4]  = { hidden, h0, h1, h0 };
    const float* hph[4]  = { h1hi, h0hi, h1hi, h0hi };
    const float* hpl[4]  = { h1lo, h0lo, h1lo, h0lo };
    float*       hnr[4]  = { h0, h1, h0, out };
    float*       hnh[4]  = { h0hi, h1hi, h0hi, h1hi };
    float*       hnl[4]  = { h0lo, h1lo, h0lo, h1lo };

    for (int s = 0; s < 4; s++) {
        k_mma_a<<<dim3(4, BQ), 256, 104448>>>(Ahi, Alo, hph[s], hpl[s], b_ah, ahi, alo);
        k_zr<<<M2 / 64, 256, 102400>>>(
            ahi, alo, hph[s], hpl[s], Wsp,
            b_wz, b_uz, b_wr, b_ur, hpr[s], zr, rhhi, rhlo);
        k_cgate<<<M2 / 128, 256, 81920>>>(
            ahi, alo, rhhi, rhlo, Wsp,
            b_w, b_u, hpr[s], zr, hnr[s], hnh[s], hnl[s]);
    }
}

// round 8
// speedup vs baseline: 1.4869x; 1.0127x over previous
#include <cuda_runtime.h>
#include <math.h>
#include <stdint.h>

#define BQ 128
#define NQ 512
#define HQ 128
#define M2 65536

// ---------------- scratch (allocation-free rule) ----------------
__device__ float g_a [(size_t)M2 * HQ];
__device__ float g_z [(size_t)M2 * HQ];
__device__ float g_rh[(size_t)M2 * HQ];
__device__ float g_h0[(size_t)M2 * HQ];
__device__ float g_h1[(size_t)M2 * HQ];
__device__ float g_Wsp[12 * (size_t)HQ * HQ];  // [0,1]=wz [2,3]=uz [4,5]=wr [6,7]=ur [8,9]=w [10,11]=u (hi,lo)

// ---------------- helpers ----------------
__device__ __forceinline__ void cpa16(uint32_t dst, const float* src) {
    asm volatile("cp.async.cg.shared.global [%0], [%1], 16;" :: "r"(dst), "l"(src));
}
#define CP_COMMIT() asm volatile("cp.async.commit_group;" ::: "memory")
#define CP_WAIT1()  asm volatile("cp.async.wait_group 1;" ::: "memory")
#define CP_WAIT0()  asm volatile("cp.async.wait_group 0;" ::: "memory")

__device__ __forceinline__ uint32_t smem_u32(const void* p) {
    uint32_t a;
    asm("{ .reg .u64 t; cvta.to.shared.u64 t, %1; cvt.u32.u64 %0, t; }" : "=r"(a) : "l"(p));
    return a;
}
__device__ __forceinline__ uint32_t f2tf(float x) {
    uint32_t r;
    asm("cvt.rna.tf32.f32 %0, %1;" : "=r"(r) : "f"(x));
    return r;
}
__device__ __forceinline__ void fsplit(float x, float& h, float& l) {
    h = __uint_as_float(f2tf(x));
    l = __uint_as_float(f2tf(x - h));
}
__device__ __forceinline__ void fsplit4(float4 v, float4& h, float4& l) {
    fsplit(v.x, h.x, l.x); fsplit(v.y, h.y, l.y);
    fsplit(v.z, h.z, l.z); fsplit(v.w, h.w, l.w);
}
__device__ __forceinline__ void mma8(float* c, const uint32_t* a, const uint32_t* b) {
    asm volatile(
        "mma.sync.aligned.m16n8k8.row.col.f32.tf32.tf32.f32 "
        "{%0,%1,%2,%3}, {%4,%5,%6,%7}, {%8,%9}, {%0,%1,%2,%3};"
        : "+f"(c[0]), "+f"(c[1]), "+f"(c[2]), "+f"(c[3])
        : "r"(a[0]), "r"(a[1]), "r"(a[2]), "r"(a[3]), "r"(b[0]), "r"(b[1]));
}

// ---------------------------------------------------------------------------
// Weight split pre-pass (tiny; weights L2-resident thereafter)
// ---------------------------------------------------------------------------
__global__ __launch_bounds__(256)
void k_split(const float* __restrict__ s, float* __restrict__ hi,
             float* __restrict__ lo, int n4)
{
    int i = blockIdx.x * blockDim.x + threadIdx.x;
    if (i >= n4) return;
    float4 v = reinterpret_cast<const float4*>(s)[i];
    float4 h, l;
    fsplit4(v, h, l);
    reinterpret_cast<float4*>(hi)[i] = h;
    reinterpret_cast<float4*>(lo)[i] = l;
}

// ---------------------------------------------------------------------------
// a-GEMM: a[b,n,h] = sum_m A[b,m,n]*h[b,m,h] + bias[h]  (raw in, raw out)
// K-major smem [k][i], stride 136 w, K-chunk 16, C=32.
// Raw operands staged in regs (LDG.128), split at STS time. 2-stage smem.
// smem = 2 * 4 tiles * 16*136*4 = 69632 B.
// ---------------------------------------------------------------------------
#define AT_W 2176            // words per tile (16*136)
#define AS_W 8704            // words per stage (4 tiles)
__global__ __launch_bounds__(256)
void k_mma_a(const float* __restrict__ A, const float* __restrict__ Hp,
             const float* __restrict__ bias, float* __restrict__ outp)
{
    extern __shared__ uint32_t su[];
    const int t = threadIdx.x, lane = t & 31, wid = t >> 5;
    const int wi = wid & 1, wj = wid >> 1;
    const int g = lane >> 2, tq = lane & 3;
    const int b = blockIdx.y, n0 = blockIdx.x * 128;

    const float* Ab = A  + (size_t)b * NQ * NQ + n0;
    const float* Hb = Hp + (size_t)b * NQ * HQ;

    float acc[4][4][4];
#pragma unroll
    for (int a_ = 0; a_ < 4; a_++)
#pragma unroll
        for (int b_ = 0; b_ < 4; b_++)
#pragma unroll
            for (int c_ = 0; c_ < 4; c_++) acc[a_][b_][c_] = 0.f;

    const int C = 32;
    float4 rA[2], rH[2];

#define A_LDG(cc)                                                              \
    {                                                                          \
        _Pragma("unroll")                                                      \
        for (int p = 0; p < 2; p++) {                                          \
            const int idx = t + p * 256;                                       \
            const int k = idx >> 5, c4 = idx & 31;                             \
            rA[p] = *reinterpret_cast<const float4*>(                          \
                Ab + (size_t)((cc) * 16 + k) * NQ + c4 * 4);                   \
            rH[p] = *reinterpret_cast<const float4*>(                          \
                Hb + (size_t)((cc) * 16 + k) * HQ + c4 * 4);                   \
        }                                                                      \
    }
#define A_STS(st)                                                              \
    {                                                                          \
        uint32_t* s0 = su + (st) * AS_W;                                       \
        _Pragma("unroll")                                                      \
        for (int p = 0; p < 2; p++) {                                          \
            const int idx = t + p * 256;                                       \
            const int k = idx >> 5, c4 = idx & 31;                             \
            const int off = k * 136 + c4 * 4;                                  \
            float4 h, l;                                                       \
            fsplit4(rA[p], h, l);                                              \
            *reinterpret_cast<float4*>(s0 + off) = h;                          \
            *reinterpret_cast<float4*>(s0 + AT_W + off) = l;                   \
            fsplit4(rH[p], h, l);                                              \
            *reinterpret_cast<float4*>(s0 + 2 * AT_W + off) = h;               \
            *reinterpret_cast<float4*>(s0 + 3 * AT_W + off) = l;               \
        }                                                                      \
    }

    A_LDG(0);
    for (int c = 0; c < C; c++) {
        const int sc = c & 1;
        A_STS(sc);
        if (c + 1 < C) A_LDG(c + 1);
        __syncthreads();
        const uint32_t* Xh = su + sc * AS_W;
        const uint32_t* Xl = Xh + AT_W;
        const uint32_t* Wh = Xh + 2 * AT_W;
        const uint32_t* Wl = Xh + 3 * AT_W;
#pragma unroll
        for (int kb = 0; kb < 16; kb += 8) {
            uint32_t ah[4][4], al[4][4], bh[4][2], bl[4][2];
#pragma unroll
            for (int mf = 0; mf < 4; mf++) {
                const int r = wi * 64 + mf * 16 + g;
                ah[mf][0] = Xh[(kb + tq) * 136 + r];
                ah[mf][1] = Xh[(kb + tq) * 136 + r + 8];
                ah[mf][2] = Xh[(kb + tq + 4) * 136 + r];
                ah[mf][3] = Xh[(kb + tq + 4) * 136 + r + 8];
                al[mf][0] = Xl[(kb + tq) * 136 + r];
                al[mf][1] = Xl[(kb + tq) * 136 + r + 8];
                al[mf][2] = Xl[(kb + tq + 4) * 136 + r];
                al[mf][3] = Xl[(kb + tq + 4) * 136 + r + 8];
            }
#pragma unroll
            for (int nf = 0; nf < 4; nf++) {
                const int cj = wj * 32 + nf * 8 + g;
                bh[nf][0] = Wh[(kb + tq) * 136 + cj];
                bh[nf][1] = Wh[(kb + tq + 4) * 136 + cj];
                bl[nf][0] = Wl[(kb + tq) * 136 + cj];
                bl[nf][1] = Wl[(kb + tq + 4) * 136 + cj];
            }
            // term-major: 16 independent MMAs between same-acc reuses
#pragma unroll
            for (int nf = 0; nf < 4; nf++)
#pragma unroll
                for (int mf = 0; mf < 4; mf++) mma8(acc[mf][nf], ah[mf], bh[nf]);
#pragma unroll
            for (int nf = 0; nf < 4; nf++)
#pragma unroll
                for (int mf = 0; mf < 4; mf++) mma8(acc[mf][nf], al[mf], bh[nf]);
#pragma unroll
            for (int nf = 0; nf < 4; nf++)
#pragma unroll
                for (int mf = 0; mf < 4; mf++) mma8(acc[mf][nf], ah[mf], bl[nf]);
        }
        __syncthreads();
    }
#undef A_LDG
#undef A_STS

    const size_t obase = (size_t)b * NQ * HQ;
#pragma unroll
    for (int mf = 0; mf < 4; mf++) {
#pragma unroll
        for (int h2 = 0; h2 < 2; h2++) {
            const int i = n0 + wi * 64 + mf * 16 + g + h2 * 8;
            const size_t rb = obase + (size_t)i * HQ;
#pragma unroll
            for (int nf = 0; nf < 4; nf++) {
                const int j = wj * 32 + nf * 8 + 2 * tq;
                const float2 bb = *reinterpret_cast<const float2*>(bias + j);
                float2 v;
                v.x = acc[mf][nf][h2 * 2 + 0] + bb.x;
                v.y = acc[mf][nf][h2 * 2 + 1] + bb.y;
                *reinterpret_cast<float2*>(outp + rb + j) = v;
            }
        }
    }
}

// ---------------------------------------------------------------------------
// Fused z+r: [z|r] = a@[wz|wr]^T + h@[uz|ur]^T (+biases)
//   cols 0..127  -> z = sigmoid(.)          -> zout
//   cols 128..255-> rh = sigmoid(.)*h       -> rhout   (both raw)
// CTA 64 rows x 256 cols, 256 thr, warp tile 64x32. K-chunk 16, C=16.
// X raw via LDG/split/STS; W pre-split via cp.async. 2-stage.
// stage words: Xh 1280, Xl 1280, Wh 5120, Wl 5120 = 12800 -> 102400 B total.
// ---------------------------------------------------------------------------
#define ZT_X 1280
#define ZT_W 5120
#define ZS_W 12800
__global__ __launch_bounds__(256)
void k_zr(const float* __restrict__ ap, const float* __restrict__ hp,
          const float* __restrict__ Wsp,
          const float* __restrict__ b_wz, const float* __restrict__ b_uz,
          const float* __restrict__ b_wr, const float* __restrict__ b_ur,
          float* __restrict__ zout, float* __restrict__ rhout)
{
    extern __shared__ uint32_t su[];
    const uint32_t sb = smem_u32(su);
    const int t = threadIdx.x, lane = t & 31, wj = t >> 5;
    const int g = lane >> 2, tq = lane & 3;
    const int i0 = blockIdx.x * 64;
    const int S = HQ * HQ;

    float acc[4][4][4];
#pragma unroll
    for (int a_ = 0; a_ < 4; a_++)
#pragma unroll
        for (int b_ = 0; b_ < 4; b_++)
#pragma unroll
            for (int c_ = 0; c_ < 4; c_++) acc[a_][b_][c_] = 0.f;

    const int C = 16;
    float4 rX;

#define Z_LDGX(cc)                                                             \
    {                                                                          \
        const int half = (cc) >> 3;                                            \
        const int kc = ((cc) & 7) * 16;                                        \
        const float* xp = (half ? hp : ap) + (size_t)i0 * HQ + kc;             \
        const int row = t >> 2, f4 = t & 3;                                    \
        rX = *reinterpret_cast<const float4*>(xp + (size_t)row * HQ + f4 * 4); \
    }
#define Z_STSX(st)                                                             \
    {                                                                          \
        uint32_t* s0 = su + (st) * ZS_W;                                       \
        const int row = t >> 2, f4 = t & 3;                                    \
        const int off = row * 20 + f4 * 4;                                     \
        float4 h, l;                                                           \
        fsplit4(rX, h, l);                                                     \
        *reinterpret_cast<float4*>(s0 + off) = h;                              \
        *reinterpret_cast<float4*>(s0 + ZT_X + off) = l;                       \
    }
#define Z_CPAW(cc, st)                                                         \
    {                                                                          \
        const int half = (cc) >> 3;                                            \
        const int kc = ((cc) & 7) * 16;                                        \
        const float* w1h = Wsp + (half ? 2 : 0) * S + kc;                      \
        const float* w1l = Wsp + (half ? 3 : 1) * S + kc;                      \
        const float* w2h = Wsp + (half ? 6 : 4) * S + kc;                      \
        const float* w2l = Wsp + (half ? 7 : 5) * S + kc;                      \
        const uint32_t s0 = sb + (uint32_t)(st) * ZS_W * 4;                    \
        _Pragma("unroll")                                                      \
        for (int p = 0; p < 4; p++) {                                          \
            const int idx = t + p * 256;                                       \
            const int row = idx >> 2, f4 = idx & 3;                            \
            const uint32_t off = (uint32_t)(row * 20 + f4 * 4) * 4;            \
            const float* sh = (row < 128) ? (w1h + (size_t)row * HQ)           \
                                          : (w2h + (size_t)(row - 128) * HQ);  \
            const float* sl = (row < 128) ? (w1l + (size_t)row * HQ)           \
                                          : (w2l + (size_t)(row - 128) * HQ);  \
            cpa16(s0 + 2 * ZT_X * 4 + off,          sh + f4 * 4);              \
            cpa16(s0 + (2 * ZT_X + ZT_W) * 4 + off, sl + f4 * 4);              \
        }                                                                      \
        CP_COMMIT();                                                           \
    }

    Z_LDGX(0);
    Z_CPAW(0, 0);
    for (int c = 0; c < C; c++) {
        const int sc = c & 1;
        Z_STSX(sc);
        if (c + 1 < C) { Z_LDGX(c + 1); Z_CPAW(c + 1, (c + 1) & 1); CP_WAIT1(); }
        else           { CP_WAIT0(); }
        __syncthreads();
        const uint32_t* Xh = su + sc * ZS_W;
        const uint32_t* Xl = Xh + ZT_X;
        const uint32_t* Wh = Xh + 2 * ZT_X;
        const uint32_t* Wl = Wh + ZT_W;
#pragma unroll
        for (int kb = 0; kb < 16; kb += 8) {
            uint32_t ah[4][4], al[4][4], bh[4][2], bl[4][2];
#pragma unroll
            for (int mf = 0; mf < 4; mf++) {
                const int r = mf * 16 + g;
                ah[mf][0] = Xh[r * 20 + kb + tq];
                ah[mf][1] = Xh[(r + 8) * 20 + kb + tq];
                ah[mf][2] = Xh[r * 20 + kb + tq + 4];
                ah[mf][3] = Xh[(r + 8) * 20 + kb + tq + 4];
                al[mf][0] = Xl[r * 20 + kb + tq];
                al[mf][1] = Xl[(r + 8) * 20 + kb + tq];
                al[mf][2] = Xl[r * 20 + kb + tq + 4];
                al[mf][3] = Xl[(r + 8) * 20 + kb + tq + 4];
            }
#pragma unroll
            for (int nf = 0; nf < 4; nf++) {
                const int cj = wj * 32 + nf * 8 + g;
                bh[nf][0] = Wh[cj * 20 + kb + tq];
                bh[nf][1] = Wh[cj * 20 + kb + tq + 4];
                bl[nf][0] = Wl[cj * 20 + kb + tq];
                bl[nf][1] = Wl[cj * 20 + kb + tq + 4];
            }
#pragma unroll
            for (int nf = 0; nf < 4; nf++)
#pragma unroll
                for (int mf = 0; mf < 4; mf++) mma8(acc[mf][nf], ah[mf], bh[nf]);
#pragma unroll
            for (int nf = 0; nf < 4; nf++)
#pragma unroll
                for (int mf = 0; mf < 4; mf++) mma8(acc[mf][nf], al[mf], bh[nf]);
#pragma unroll
            for (int nf = 0; nf < 4; nf++)
#pragma unroll
                for (int mf = 0; mf < 4; mf++) mma8(acc[mf][nf], ah[mf], bl[nf]);
        }
        __syncthreads();
    }
#undef Z_LDGX
#undef Z_STSX
#undef Z_CPAW

#pragma unroll
    for (int mf = 0; mf < 4; mf++) {
#pragma unroll
        for (int h2 = 0; h2 < 2; h2++) {
            const int i = i0 + mf * 16 + g + h2 * 8;
            const size_t rb = (size_t)i * HQ;
#pragma unroll
            for (int nf = 0; nf < 4; nf++) {
                const int j = wj * 32 + nf * 8 + 2 * tq;
                if (wj < 4) {
                    const float2 bb1 = *reinterpret_cast<const float2*>(b_wz + j);
                    const float2 bb2 = *reinterpret_cast<const float2*>(b_uz + j);
                    float v0 = acc[mf][nf][h2 * 2 + 0] + bb1.x + bb2.x;
                    float v1 = acc[mf][nf][h2 * 2 + 1] + bb1.y + bb2.y;
                    float2 o;
                    o.x = 1.f / (1.f + __expf(-v0));
                    o.y = 1.f / (1.f + __expf(-v1));
                    *reinterpret_cast<float2*>(zout + rb + j) = o;
                } else {
                    const int jj = j - 128;
                    const float2 bb1 = *reinterpret_cast<const float2*>(b_wr + jj);
                    const float2 bb2 = *reinterpret_cast<const float2*>(b_ur + jj);
                    float v0 = acc[mf][nf][h2 * 2 + 0] + bb1.x + bb2.x;
                    float v1 = acc[mf][nf][h2 * 2 + 1] + bb1.y + bb2.y;
                    const float2 hv = *reinterpret_cast<const float2*>(hp + rb + jj);
                    float2 o;
                    o.x = hv.x * (1.f / (1.f + __expf(-v0)));
                    o.y = hv.y * (1.f / (1.f + __expf(-v1)));
                    *reinterpret_cast<float2*>(rhout + rb + jj) = o;
                }
            }
        }
    }
}

// ---------------------------------------------------------------------------
// c-gate: D = a@w^T + rh@u^T (+b); h' = (1-z)h + z tanh(D)  (raw out)
// CTA 128x128, K-chunk 16, C=16, 2-stage, stride 20 w. smem 81920 B.
// ---------------------------------------------------------------------------
#define GT_W 2560
#define GS_W 10240
__global__ __launch_bounds__(256)
void k_cgate(const float* __restrict__ ap, const float* __restrict__ rhp,
             const float* __restrict__ Wsp,
             const float* __restrict__ b1, const float* __restrict__ b2,
             const float* __restrict__ hp, const float* __restrict__ zp,
             float* __restrict__ outp)
{
    extern __shared__ uint32_t su[];
    const uint32_t sb = smem_u32(su);
    const int t = threadIdx.x, lane = t & 31, wid = t >> 5;
    const int wi = wid & 1, wj = wid >> 1;
    const int g = lane >> 2, tq = lane & 3;
    const int i0 = blockIdx.x * 128;
    const int S = HQ * HQ;

    float acc[4][4][4];
#pragma unroll
    for (int a_ = 0; a_ < 4; a_++)
#pragma unroll
        for (int b_ = 0; b_ < 4; b_++)
#pragma unroll
            for (int c_ = 0; c_ < 4; c_++) acc[a_][b_][c_] = 0.f;

    const int C = 16;
    float4 rX[2];

#define G_LDGX(cc)                                                             \
    {                                                                          \
        const int gg = (cc) >> 3;                                              \
        const int kc = ((cc) & 7) * 16;                                        \
        const float* xp = (gg ? rhp : ap) + (size_t)i0 * HQ + kc;              \
        _Pragma("unroll")                                                      \
        for (int p = 0; p < 2; p++) {                                          \
            const int idx = t + p * 256;                                       \
            const int row = idx >> 2, f4 = idx & 3;                            \
            rX[p] = *reinterpret_cast<const float4*>(                          \
                xp + (size_t)row * HQ + f4 * 4);                               \
        }                                                                      \
    }
#define G_STSX(st)                                                             \
    {                                                                          \
        uint32_t* s0 = su + (st) * GS_W;                                       \
        _Pragma("unroll")                                                      \
        for (int p = 0; p < 2; p++) {                                          \
            const int idx = t + p * 256;                                       \
            const int row = idx >> 2, f4 = idx & 3;                            \
            const int off = row * 20 + f4 * 4;                                 \
            float4 h, l;                                                       \
            fsplit4(rX[p], h, l);                                              \
            *reinterpret_cast<float4*>(s0 + off) = h;                          \
            *reinterpret_cast<float4*>(s0 + GT_W + off) = l;                   \
        }                                                                      \
    }
#define G_CPAW(cc, st)                                                         \
    {                                                                          \
        const int gg = (cc) >> 3;                                              \
        const int kc = ((cc) & 7) * 16;                                        \
        const float* wh_ = Wsp + (gg ? 10 : 8) * S + kc;                       \
        const float* wl_ = Wsp + (gg ? 11 : 9) * S + kc;                       \
        const uint32_t s0 = sb + (uint32_t)(st) * GS_W * 4;                    \
        _Pragma("unroll")                                                      \
        for (int p = 0; p < 2; p++) {                                          \
            const int idx = t + p * 256;                                       \
            const int row = idx >> 2, f4 = idx & 3;                            \
            const uint32_t off = (uint32_t)(row * 20 + f4 * 4) * 4;            \
            cpa16(s0 + 2 * GT_W * 4 + off, wh_ + (size_t)row * HQ + f4 * 4);   \
            cpa16(s0 + 3 * GT_W * 4 + off, wl_ + (size_t)row * HQ + f4 * 4);   \
        }                                                                      \
        CP_COMMIT();                                                           \
    }

    G_LDGX(0);
    G_CPAW(0, 0);
    for (int c = 0; c < C; c++) {
        const int sc = c & 1;
        G_STSX(sc);
        if (c + 1 < C) { G_LDGX(c + 1); G_CPAW(c + 1, (c + 1) & 1); CP_WAIT1(); }
        else           { CP_WAIT0(); }
        __syncthreads();
        const uint32_t* Xh = su + sc * GS_W;
        const uint32_t* Xl = Xh + GT_W;
        const uint32_t* Wh = Xh + 2 * GT_W;
        const uint32_t* Wl = Xh + 3 * GT_W;
#pragma unroll
        for (int kb = 0; kb < 16; kb += 8) {
            uint32_t ah[4][4], al[4][4], bh[4][2], bl[4][2];
#pragma unroll
            for (int mf = 0; mf < 4; mf++) {
                const int r = wi * 64 + mf * 16 + g;
                ah[mf][0] = Xh[r * 20 + kb + tq];
                ah[mf][1] = Xh[(r + 8) * 20 + kb + tq];
                ah[mf][2] = Xh[r * 20 + kb + tq + 4];
                ah[mf][3] = Xh[(r + 8) * 20 + kb + tq + 4];
                al[mf][0] = Xl[r * 20 + kb + tq];
                al[mf][1] = Xl[(r + 8) * 20 + kb + tq];
                al[mf][2] = Xl[r * 20 + kb + tq + 4];
                al[mf][3] = Xl[(r + 8) * 20 + kb + tq + 4];
            }
#pragma unroll
            for (int nf = 0; nf < 4; nf++) {
                const int cj = wj * 32 + nf * 8 + g;
                bh[nf][0] = Wh[cj * 20 + kb + tq];
                bh[nf][1] = Wh[cj * 20 + kb + tq + 4];
                bl[nf][0] = Wl[cj * 20 + kb + tq];
                bl[nf][1] = Wl[cj * 20 + kb + tq + 4];
            }
#pragma unroll
            for (int nf = 0; nf < 4; nf++)
#pragma unroll
                for (int mf = 0; mf < 4; mf++) mma8(acc[mf][nf], ah[mf], bh[nf]);
#pragma unroll
            for (int nf = 0; nf < 4; nf++)
#pragma unroll
                for (int mf = 0; mf < 4; mf++) mma8(acc[mf][nf], al[mf], bh[nf]);
#pragma unroll
            for (int nf = 0; nf < 4; nf++)
#pragma unroll
                for (int mf = 0; mf < 4; mf++) mma8(acc[mf][nf], ah[mf], bl[nf]);
        }
        __syncthreads();
    }
#undef G_LDGX
#undef G_STSX
#undef G_CPAW

#pragma unroll
    for (int mf = 0; mf < 4; mf++) {
#pragma unroll
        for (int h2 = 0; h2 < 2; h2++) {
            const int i = i0 + wi * 64 + mf * 16 + g + h2 * 8;
            const size_t rb = (size_t)i * HQ;
#pragma unroll
            for (int nf = 0; nf < 4; nf++) {
                const int j = wj * 32 + nf * 8 + 2 * tq;
                const float2 bb1 = *reinterpret_cast<const float2*>(b1 + j);
                const float2 bb2 = *reinterpret_cast<const float2*>(b2 + j);
                float v0 = acc[mf][nf][h2 * 2 + 0] + bb1.x + bb2.x;
                float v1 = acc[mf][nf][h2 * 2 + 1] + bb1.y + bb2.y;
                const float2 hv = *reinterpret_cast<const float2*>(hp + rb + j);
                const float2 zz = *reinterpret_cast<const float2*>(zp + rb + j);
                float2 o;
                o.x = (1.f - zz.x) * hv.x + zz.x * tanhf(v0);
                o.y = (1.f - zz.y) * hv.y + zz.y * tanhf(v1);
                *reinterpret_cast<float2*>(outp + rb + j) = o;
            }
        }
    }
}

// ---------------------------------------------------------------------------
// Host launcher
// ---------------------------------------------------------------------------
extern "C" void kernel_launch(void* const* d_in, const int* in_sizes, int n_in,
                              void* d_out, int out_size)
{
    const float* A      = (const float*)d_in[0];
    const float* hidden = (const float*)d_in[1];
    const float* b_ah   = (const float*)d_in[2];
    const float* w_z    = (const float*)d_in[3];
    const float* b_wz   = (const float*)d_in[4];
    const float* u_z    = (const float*)d_in[5];
    const float* b_uz   = (const float*)d_in[6];
    const float* w_r    = (const float*)d_in[7];
    const float* b_wr   = (const float*)d_in[8];
    const float* u_r    = (const float*)d_in[9];
    const float* b_ur   = (const float*)d_in[10];
    const float* w      = (const float*)d_in[11];
    const float* b_w    = (const float*)d_in[12];
    const float* u      = (const float*)d_in[13];
    const float* b_u    = (const float*)d_in[14];
    float* out = (float*)d_out;

    float *ga, *gz, *grh, *h0, *h1, *Wsp;
    cudaGetSymbolAddress((void**)&ga,  g_a);
    cudaGetSymbolAddress((void**)&gz,  g_z);
    cudaGetSymbolAddress((void**)&grh, g_rh);
    cudaGetSymbolAddress((void**)&h0,  g_h0);
    cudaGetSymbolAddress((void**)&h1,  g_h1);
    cudaGetSymbolAddress((void**)&Wsp, g_Wsp);

    cudaFuncSetAttribute(k_mma_a, cudaFuncAttributeMaxDynamicSharedMemorySize, 69632);
    cudaFuncSetAttribute(k_zr,    cudaFuncAttributeMaxDynamicSharedMemorySize, 102400);
    cudaFuncSetAttribute(k_cgate, cudaFuncAttributeMaxDynamicSharedMemorySize, 81920);

    const int S = HQ * HQ;   // 16384
    k_split<<<S / 1024, 256>>>(w_z, Wsp + 0 * S,  Wsp + 1 * S,  S / 4);
    k_split<<<S / 1024, 256>>>(u_z, Wsp + 2 * S,  Wsp + 3 * S,  S / 4);
    k_split<<<S / 1024, 256>>>(w_r, Wsp + 4 * S,  Wsp + 5 * S,  S / 4);
    k_split<<<S / 1024, 256>>>(u_r, Wsp + 6 * S,  Wsp + 7 * S,  S / 4);
    k_split<<<S / 1024, 256>>>(w,   Wsp + 8 * S,  Wsp + 9 * S,  S / 4);
    k_split<<<S / 1024, 256>>>(u,   Wsp + 10 * S, Wsp + 11 * S, S / 4);

    const float* hpr[4] = { hidden, h0, h1, h0 };
    float*       hnr[4] = { h0, h1, h0, out };

    for (int s = 0; s < 4; s++) {
        const float* hp = hpr[s];
        k_mma_a<<<dim3(4, BQ), 256, 69632>>>(A, hp, b_ah, ga);
        k_zr<<<M2 / 64, 256, 102400>>>(ga, hp, Wsp, b_wz, b_uz, b_wr, b_ur, gz, grh);
        k_cgate<<<M2 / 128, 256, 81920>>>(ga, grh, Wsp, b_w, b_u, hp, gz, hnr[s]);
    }
}

// round 9
// speedup vs baseline: 2.5625x; 1.7234x over previous
#include <cuda_runtime.h>
#include <cuda_fp16.h>
#include <math.h>
#include <stdint.h>

#define BQ 128
#define NQ 512
#define HQ 128
#define M2 65536

// ---------------- scratch (allocation-free rule) ----------------
__device__ float    g_a [(size_t)M2 * HQ];
__device__ float    g_z [(size_t)M2 * HQ];
__device__ float    g_rh[(size_t)M2 * HQ];
__device__ float    g_h0[(size_t)M2 * HQ];
__device__ float    g_h1[(size_t)M2 * HQ];
__device__ uint32_t g_Wh[12 * (size_t)HQ * HQ / 2];  // packed half2 k-pairs:
// [0,1]=wz(hi,lo) [2,3]=uz [4,5]=wr [6,7]=ur [8,9]=w [10,11]=u ; each 8192 words

// ---------------- helpers ----------------
__device__ __forceinline__ void cpa16(uint32_t dst, const void* src) {
    asm volatile("cp.async.cg.shared.global [%0], [%1], 16;" :: "r"(dst), "l"(src));
}
#define CP_COMMIT() asm volatile("cp.async.commit_group;" ::: "memory")
#define CP_WAIT1()  asm volatile("cp.async.wait_group 1;" ::: "memory")
#define CP_WAIT0()  asm volatile("cp.async.wait_group 0;" ::: "memory")

__device__ __forceinline__ uint32_t smem_u32(const void* p) {
    uint32_t a;
    asm("{ .reg .u64 t; cvta.to.shared.u64 t, %1; cvt.u32.u64 %0, t; }" : "=r"(a) : "l"(p));
    return a;
}
// Split (x,y) into packed fp16 hi pair + fp16 residual pair (Markidis split).
__device__ __forceinline__ void hsplit2(float x, float y, uint32_t& hi, uint32_t& lo) {
    __half hx = __float2half_rn(x);
    __half hy = __float2half_rn(y);
    __half lx = __float2half_rn(x - __half2float(hx));
    __half ly = __float2half_rn(y - __half2float(hy));
    __half2 H = __halves2half2(hx, hy);
    __half2 L = __halves2half2(lx, ly);
    hi = *reinterpret_cast<uint32_t*>(&H);
    lo = *reinterpret_cast<uint32_t*>(&L);
}
__device__ __forceinline__ void mma16(float* c, const uint32_t* a, const uint32_t* b) {
    asm volatile(
        "mma.sync.aligned.m16n8k16.row.col.f32.f16.f16.f32 "
        "{%0,%1,%2,%3}, {%4,%5,%6,%7}, {%8,%9}, {%0,%1,%2,%3};"
        : "+f"(c[0]), "+f"(c[1]), "+f"(c[2]), "+f"(c[3])
        : "r"(a[0]), "r"(a[1]), "r"(a[2]), "r"(a[3]), "r"(b[0]), "r"(b[1]));
}

// ---------------------------------------------------------------------------
// Weight split pre-pass: fp32 [j][128] -> packed half2 k-pairs [j][64] hi + lo
// ---------------------------------------------------------------------------
__global__ __launch_bounds__(256)
void k_splith(const float* __restrict__ s, uint32_t* __restrict__ hi,
              uint32_t* __restrict__ lo, int n4)
{
    int i = blockIdx.x * blockDim.x + threadIdx.x;
    if (i >= n4) return;
    float4 v = reinterpret_cast<const float4*>(s)[i];
    uint32_t h0, l0, h1, l1;
    hsplit2(v.x, v.y, h0, l0);
    hsplit2(v.z, v.w, h1, l1);
    uint2 H; H.x = h0; H.y = h1;
    uint2 L; L.x = l0; L.y = l1;
    reinterpret_cast<uint2*>(hi)[i] = H;
    reinterpret_cast<uint2*>(lo)[i] = L;
}

// ---------------------------------------------------------------------------
// a-GEMM: a[b,n,h] = sum_m A[b,m,n]*h[b,m,h] + bias[h]  (raw fp32 in/out)
// K-major smem [kpair][i], stride 136 words, K-chunk 16 (8 pairs), C=32.
// Tiles: Ahi, Alo, Hhi, Hlo (8x136 words each). 2-stage. smem 34816 B.
// ---------------------------------------------------------------------------
#define AT_W 1088            // words per tile (8*136)
#define AS_W 4352            // words per stage (4 tiles)
__global__ __launch_bounds__(256)
void k_mma_a(const float* __restrict__ A, const float* __restrict__ Hp,
             const float* __restrict__ bias, float* __restrict__ outp)
{
    extern __shared__ uint32_t su[];
    const int t = threadIdx.x, lane = t & 31, wid = t >> 5;
    const int wi = wid & 1, wj = wid >> 1;
    const int g = lane >> 2, tq = lane & 3;
    const int b = blockIdx.y, n0 = blockIdx.x * 128;

    const float* Ab = A  + (size_t)b * NQ * NQ + n0;
    const float* Hb = Hp + (size_t)b * NQ * HQ;

    float acc[4][4][4];
#pragma unroll
    for (int a_ = 0; a_ < 4; a_++)
#pragma unroll
        for (int b_ = 0; b_ < 4; b_++)
#pragma unroll
            for (int c_ = 0; c_ < 4; c_++) acc[a_][b_][c_] = 0.f;

    const int C = 32;
    const int kp = t >> 5;       // 0..7 (k-pair within chunk)
    const int c4 = t & 31;       // float4 col index 0..31
    float4 rA0, rA1, rH0, rH1;

#define A_LDG(cc)                                                              \
    {                                                                          \
        const int m0 = (cc) * 16 + kp * 2;                                     \
        rA0 = *reinterpret_cast<const float4*>(Ab + (size_t)m0 * NQ + c4 * 4); \
        rA1 = *reinterpret_cast<const float4*>(Ab + (size_t)(m0+1)*NQ + c4*4); \
        rH0 = *reinterpret_cast<const float4*>(Hb + (size_t)m0 * HQ + c4 * 4); \
        rH1 = *reinterpret_cast<const float4*>(Hb + (size_t)(m0+1)*HQ + c4*4); \
    }
#define A_STS(st)                                                              \
    {                                                                          \
        uint32_t* s0 = su + (st) * AS_W;                                       \
        const int off = kp * 136 + c4 * 4;                                     \
        uint4 H, L;                                                            \
        hsplit2(rA0.x, rA1.x, H.x, L.x); hsplit2(rA0.y, rA1.y, H.y, L.y);      \
        hsplit2(rA0.z, rA1.z, H.z, L.z); hsplit2(rA0.w, rA1.w, H.w, L.w);      \
        *reinterpret_cast<uint4*>(s0 + off) = H;                               \
        *reinterpret_cast<uint4*>(s0 + AT_W + off) = L;                        \
        hsplit2(rH0.x, rH1.x, H.x, L.x); hsplit2(rH0.y, rH1.y, H.y, L.y);      \
        hsplit2(rH0.z, rH1.z, H.z, L.z); hsplit2(rH0.w, rH1.w, H.w, L.w);      \
        *reinterpret_cast<uint4*>(s0 + 2 * AT_W + off) = H;                    \
        *reinterpret_cast<uint4*>(s0 + 3 * AT_W + off) = L;                    \
    }

    A_LDG(0);
    for (int c = 0; c < C; c++) {
        const int sc = c & 1;
        A_STS(sc);
        if (c + 1 < C) A_LDG(c + 1);
        __syncthreads();
        const uint32_t* Xh = su + sc * AS_W;
        const uint32_t* Xl = Xh + AT_W;
        const uint32_t* Wh = Xh + 2 * AT_W;
        const uint32_t* Wl = Xh + 3 * AT_W;
        uint32_t ah[4][4], al[4][4], bh[4][2], bl[4][2];
#pragma unroll
        for (int mf = 0; mf < 4; mf++) {
            const int r = wi * 64 + mf * 16 + g;
            ah[mf][0] = Xh[tq * 136 + r];
            ah[mf][1] = Xh[tq * 136 + r + 8];
            ah[mf][2] = Xh[(tq + 4) * 136 + r];
            ah[mf][3] = Xh[(tq + 4) * 136 + r + 8];
            al[mf][0] = Xl[tq * 136 + r];
            al[mf][1] = Xl[tq * 136 + r + 8];
            al[mf][2] = Xl[(tq + 4) * 136 + r];
            al[mf][3] = Xl[(tq + 4) * 136 + r + 8];
        }
#pragma unroll
        for (int nf = 0; nf < 4; nf++) {
            const int cj = wj * 32 + nf * 8 + g;
            bh[nf][0] = Wh[tq * 136 + cj];
            bh[nf][1] = Wh[(tq + 4) * 136 + cj];
            bl[nf][0] = Wl[tq * 136 + cj];
            bl[nf][1] = Wl[(tq + 4) * 136 + cj];
        }
#pragma unroll
        for (int nf = 0; nf < 4; nf++)
#pragma unroll
            for (int mf = 0; mf < 4; mf++) mma16(acc[mf][nf], ah[mf], bh[nf]);
#pragma unroll
        for (int nf = 0; nf < 4; nf++)
#pragma unroll
            for (int mf = 0; mf < 4; mf++) mma16(acc[mf][nf], al[mf], bh[nf]);
#pragma unroll
        for (int nf = 0; nf < 4; nf++)
#pragma unroll
            for (int mf = 0; mf < 4; mf++) mma16(acc[mf][nf], ah[mf], bl[nf]);
        __syncthreads();
    }
#undef A_LDG
#undef A_STS

    const size_t obase = (size_t)b * NQ * HQ;
#pragma unroll
    for (int mf = 0; mf < 4; mf++) {
#pragma unroll
        for (int h2 = 0; h2 < 2; h2++) {
            const int i = n0 + wi * 64 + mf * 16 + g + h2 * 8;
            const size_t rb = obase + (size_t)i * HQ;
#pragma unroll
            for (int nf = 0; nf < 4; nf++) {
                const int j = wj * 32 + nf * 8 + 2 * tq;
                const float2 bb = *reinterpret_cast<const float2*>(bias + j);
                float2 v;
                v.x = acc[mf][nf][h2 * 2 + 0] + bb.x;
                v.y = acc[mf][nf][h2 * 2 + 1] + bb.y;
                *reinterpret_cast<float2*>(outp + rb + j) = v;
            }
        }
    }
}

// ---------------------------------------------------------------------------
// Fused z+r: [z|r] = a@[wz|wr]^T + h@[uz|ur]^T (+biases)
// CTA 64 rows x 256 cols, warp tile 64x32. M-major smem [i][kpair], stride 12.
// Tiles: Xh/Xl 64x12, Wh/Wl 256x12. 2-stage. smem 61440 B.
// ---------------------------------------------------------------------------
#define ZT_X 768             // 64*12
#define ZT_W 3072            // 256*12
#define ZS_W 7680
__global__ __launch_bounds__(256)
void k_zr(const float* __restrict__ ap, const float* __restrict__ hp,
          const uint32_t* __restrict__ Wsp,
          const float* __restrict__ b_wz, const float* __restrict__ b_uz,
          const float* __restrict__ b_wr, const float* __restrict__ b_ur,
          float* __restrict__ zout, float* __restrict__ rhout)
{
    extern __shared__ uint32_t su[];
    const uint32_t sb = smem_u32(su);
    const int t = threadIdx.x, lane = t & 31, wj = t >> 5;
    const int g = lane >> 2, tq = lane & 3;
    const int i0 = blockIdx.x * 64;
    const int SW = HQ * HQ / 2;   // 8192 packed words per matrix

    float acc[4][4][4];
#pragma unroll
    for (int a_ = 0; a_ < 4; a_++)
#pragma unroll
        for (int b_ = 0; b_ < 4; b_++)
#pragma unroll
            for (int c_ = 0; c_ < 4; c_++) acc[a_][b_][c_] = 0.f;

    const int C = 16;
    float4 rX;
    const int xrow = t >> 2, xf4 = t & 3;

#define Z_LDGX(cc)                                                             \
    {                                                                          \
        const int half = (cc) >> 3;                                            \
        const int kc = ((cc) & 7) * 16;                                        \
        const float* xp = (half ? hp : ap) + (size_t)i0 * HQ + kc;             \
        rX = *reinterpret_cast<const float4*>(xp + (size_t)xrow*HQ + xf4*4);   \
    }
#define Z_STSX(st)                                                             \
    {                                                                          \
        uint32_t* s0 = su + (st) * ZS_W;                                       \
        const int off = xrow * 12 + xf4 * 2;                                   \
        uint2 H, L;                                                            \
        hsplit2(rX.x, rX.y, H.x, L.x);                                         \
        hsplit2(rX.z, rX.w, H.y, L.y);                                         \
        *reinterpret_cast<uint2*>(s0 + off) = H;                               \
        *reinterpret_cast<uint2*>(s0 + ZT_X + off) = L;                        \
    }
#define Z_CPAW(cc, st)                                                         \
    {                                                                          \
        const int half = (cc) >> 3;                                            \
        const int kw = ((cc) & 7) * 8;                                         \
        const uint32_t* w1h = Wsp + (half ? 2 : 0) * SW + kw;                  \
        const uint32_t* w1l = Wsp + (half ? 3 : 1) * SW + kw;                  \
        const uint32_t* w2h = Wsp + (half ? 6 : 4) * SW + kw;                  \
        const uint32_t* w2l = Wsp + (half ? 7 : 5) * SW + kw;                  \
        const uint32_t s0 = sb + (uint32_t)(st) * ZS_W * 4;                    \
        _Pragma("unroll")                                                      \
        for (int p = 0; p < 2; p++) {                                          \
            const int idx = t + p * 256;                                       \
            const int row = idx >> 1, f4 = idx & 1;                            \
            const uint32_t off = (uint32_t)(row * 12 + f4 * 4) * 4;            \
            const uint32_t* sh = (row < 128) ? (w1h + (size_t)row * 64)        \
                                             : (w2h + (size_t)(row-128)*64);  \
            const uint32_t* sl = (row < 128) ? (w1l + (size_t)row * 64)        \
                                             : (w2l + (size_t)(row-128)*64);  \
            cpa16(s0 + 2 * ZT_X * 4 + off,          sh + f4 * 4);              \
            cpa16(s0 + (2 * ZT_X + ZT_W) * 4 + off, sl + f4 * 4);              \
        }                                                                      \
        CP_COMMIT();                                                           \
    }

    Z_LDGX(0);
    Z_CPAW(0, 0);
    for (int c = 0; c < C; c++) {
        const int sc = c & 1;
        Z_STSX(sc);
        if (c + 1 < C) { Z_LDGX(c + 1); Z_CPAW(c + 1, (c + 1) & 1); CP_WAIT1(); }
        else           { CP_WAIT0(); }
        __syncthreads();
        const uint32_t* Xh = su + sc * ZS_W;
        const uint32_t* Xl = Xh + ZT_X;
        const uint32_t* Wh = Xh + 2 * ZT_X;
        const uint32_t* Wl = Wh + ZT_W;
        uint32_t ah[4][4], al[4][4], bh[4][2], bl[4][2];
#pragma unroll
        for (int mf = 0; mf < 4; mf++) {
            const int r = mf * 16 + g;
            ah[mf][0] = Xh[r * 12 + tq];
            ah[mf][1] = Xh[(r + 8) * 12 + tq];
            ah[mf][2] = Xh[r * 12 + tq + 4];
            ah[mf][3] = Xh[(r + 8) * 12 + tq + 4];
            al[mf][0] = Xl[r * 12 + tq];
            al[mf][1] = Xl[(r + 8) * 12 + tq];
            al[mf][2] = Xl[r * 12 + tq + 4];
            al[mf][3] = Xl[(r + 8) * 12 + tq + 4];
        }
#pragma unroll
        for (int nf = 0; nf < 4; nf++) {
            const int cj = wj * 32 + nf * 8 + g;
            bh[nf][0] = Wh[cj * 12 + tq];
            bh[nf][1] = Wh[cj * 12 + tq + 4];
            bl[nf][0] = Wl[cj * 12 + tq];
            bl[nf][1] = Wl[cj * 12 + tq + 4];
        }
#pragma unroll
        for (int nf = 0; nf < 4; nf++)
#pragma unroll
            for (int mf = 0; mf < 4; mf++) mma16(acc[mf][nf], ah[mf], bh[nf]);
#pragma unroll
        for (int nf = 0; nf < 4; nf++)
#pragma unroll
            for (int mf = 0; mf < 4; mf++) mma16(acc[mf][nf], al[mf], bh[nf]);
#pragma unroll
        for (int nf = 0; nf < 4; nf++)
#pragma unroll
            for (int mf = 0; mf < 4; mf++) mma16(acc[mf][nf], ah[mf], bl[nf]);
        __syncthreads();
    }
#undef Z_LDGX
#undef Z_STSX
#undef Z_CPAW

#pragma unroll
    for (int mf = 0; mf < 4; mf++) {
#pragma unroll
        for (int h2 = 0; h2 < 2; h2++) {
            const int i = i0 + mf * 16 + g + h2 * 8;
            const size_t rb = (size_t)i * HQ;
#pragma unroll
            for (int nf = 0; nf < 4; nf++) {
                const int j = wj * 32 + nf * 8 + 2 * tq;
                if (wj < 4) {
                    const float2 bb1 = *reinterpret_cast<const float2*>(b_wz + j);
                    const float2 bb2 = *reinterpret_cast<const float2*>(b_uz + j);
                    float v0 = acc[mf][nf][h2 * 2 + 0] + bb1.x + bb2.x;
                    float v1 = acc[mf][nf][h2 * 2 + 1] + bb1.y + bb2.y;
                    float2 o;
                    o.x = 1.f / (1.f + __expf(-v0));
                    o.y = 1.f / (1.f + __expf(-v1));
                    *reinterpret_cast<float2*>(zout + rb + j) = o;
                } else {
                    const int jj = j - 128;
                    const float2 bb1 = *reinterpret_cast<const float2*>(b_wr + jj);
                    const float2 bb2 = *reinterpret_cast<const float2*>(b_ur + jj);
                    float v0 = acc[mf][nf][h2 * 2 + 0] + bb1.x + bb2.x;
                    float v1 = acc[mf][nf][h2 * 2 + 1] + bb1.y + bb2.y;
                    const float2 hv = *reinterpret_cast<const float2*>(hp + rb + jj);
                    float2 o;
                    o.x = hv.x * (1.f / (1.f + __expf(-v0)));
                    o.y = hv.y * (1.f / (1.f + __expf(-v1)));
                    *reinterpret_cast<float2*>(rhout + rb + jj) = o;
                }
            }
        }
    }
}

// ---------------------------------------------------------------------------
// c-gate: D = a@w^T + rh@u^T (+b); h' = (1-z)h + z tanh(D)
// CTA 128x128, M-major smem [i][kpair] stride 12, K-chunk 16, C=16, 2-stage.
// Tiles: Xh/Xl/Wh/Wl 128x12 = 1536 w each; stage 6144 w; smem 49152 B.
// ---------------------------------------------------------------------------
#define GT_W 1536
#define GS_W 6144
__global__ __launch_bounds__(256)
void k_cgate(const float* __restrict__ ap, const float* __restrict__ rhp,
             const uint32_t* __restrict__ Wsp,
             const float* __restrict__ b1, const float* __restrict__ b2,
             const float* __restrict__ hp, const float* __restrict__ zp,
             float* __restrict__ outp)
{
    extern __shared__ uint32_t su[];
    const uint32_t sb = smem_u32(su);
    const int t = threadIdx.x, lane = t & 31, wid = t >> 5;
    const int wi = wid & 1, wj = wid >> 1;
    const int g = lane >> 2, tq = lane & 3;
    const int i0 = blockIdx.x * 128;
    const int SW = HQ * HQ / 2;

    float acc[4][4][4];
#pragma unroll
    for (int a_ = 0; a_ < 4; a_++)
#pragma unroll
        for (int b_ = 0; b_ < 4; b_++)
#pragma unroll
            for (int c_ = 0; c_ < 4; c_++) acc[a_][b_][c_] = 0.f;

    const int C = 16;
    float4 rX[2];

#define G_LDGX(cc)                                                             \
    {                                                                          \
        const int gg = (cc) >> 3;                                              \
        const int kc = ((cc) & 7) * 16;                                        \
        const float* xp = (gg ? rhp : ap) + (size_t)i0 * HQ + kc;              \
        _Pragma("unroll")                                                      \
        for (int p = 0; p < 2; p++) {                                          \
            const int idx = t + p * 256;                                       \
            const int row = idx >> 2, f4 = idx & 3;                            \
            rX[p] = *reinterpret_cast<const float4*>(                          \
                xp + (size_t)row * HQ + f4 * 4);                               \
        }                                                                      \
    }
#define G_STSX(st)                                                             \
    {                                                                          \
        uint32_t* s0 = su + (st) * GS_W;                                       \
        _Pragma("unroll")                                                      \
        for (int p = 0; p < 2; p++) {                                          \
            const int idx = t + p * 256;                                       \
            const int row = idx >> 2, f4 = idx & 3;                            \
            const int off = row * 12 + f4 * 2;                                 \
            uint2 H, L;                                                        \
            hsplit2(rX[p].x, rX[p].y, H.x, L.x);                               \
            hsplit2(rX[p].z, rX[p].w, H.y, L.y);                               \
            *reinterpret_cast<uint2*>(s0 + off) = H;                           \
            *reinterpret_cast<uint2*>(s0 + GT_W + off) = L;                    \
        }                                                                      \
    }
#define G_CPAW(cc, st)                                                         \
    {                                                                          \
        const int gg = (cc) >> 3;                                              \
        const int kw = ((cc) & 7) * 8;                                         \
        const uint32_t* wh_ = Wsp + (gg ? 10 : 8) * SW + kw;                   \
        const uint32_t* wl_ = Wsp + (gg ? 11 : 9) * SW + kw;                   \
        const uint32_t s0 = sb + (uint32_t)(st) * GS_W * 4;                    \
        {                                                                      \
            const int row = t >> 1, f4 = t & 1;                                \
            const uint32_t off = (uint32_t)(row * 12 + f4 * 4) * 4;            \
            cpa16(s0 + 2 * GT_W * 4 + off, wh_ + (size_t)row * 64 + f4 * 4);   \
            cpa16(s0 + 3 * GT_W * 4 + off, wl_ + (size_t)row * 64 + f4 * 4);   \
        }                                                                      \
        CP_COMMIT();                                                           \
    }

    G_LDGX(0);
    G_CPAW(0, 0);
    for (int c = 0; c < C; c++) {
        const int sc = c & 1;
        G_STSX(sc);
        if (c + 1 < C) { G_LDGX(c + 1); G_CPAW(c + 1, (c + 1) & 1); CP_WAIT1(); }
        else           { CP_WAIT0(); }
        __syncthreads();
        const uint32_t* Xh = su + sc * GS_W;
        const uint32_t* Xl = Xh + GT_W;
        const uint32_t* Wh = Xh + 2 * GT_W;
        const uint32_t* Wl = Xh + 3 * GT_W;
        uint32_t ah[4][4], al[4][4], bh[4][2], bl[4][2];
#pragma unroll
        for (int mf = 0; mf < 4; mf++) {
            const int r = wi * 64 + mf * 16 + g;
            ah[mf][0] = Xh[r * 12 + tq];
            ah[mf][1] = Xh[(r + 8) * 12 + tq];
            ah[mf][2] = Xh[r * 12 + tq + 4];
            ah[mf][3] = Xh[(r + 8) * 12 + tq + 4];
            al[mf][0] = Xl[r * 12 + tq];
            al[mf][1] = Xl[(r + 8) * 12 + tq];
            al[mf][2] = Xl[r * 12 + tq + 4];
            al[mf][3] = Xl[(r + 8) * 12 + tq + 4];
        }
#pragma unroll
        for (int nf = 0; nf < 4; nf++) {
            const int cj = wj * 32 + nf * 8 + g;
            bh[nf][0] = Wh[cj * 12 + tq];
            bh[nf][1] = Wh[cj * 12 + tq + 4];
            bl[nf][0] = Wl[cj * 12 + tq];
            bl[nf][1] = Wl[cj * 12 + tq + 4];
        }
#pragma unroll
        for (int nf = 0; nf < 4; nf++)
#pragma unroll
            for (int mf = 0; mf < 4; mf++) mma16(acc[mf][nf], ah[mf], bh[nf]);
#pragma unroll
        for (int nf = 0; nf < 4; nf++)
#pragma unroll
            for (int mf = 0; mf < 4; mf++) mma16(acc[mf][nf], al[mf], bh[nf]);
#pragma unroll
        for (int nf = 0; nf < 4; nf++)
#pragma unroll
            for (int mf = 0; mf < 4; mf++) mma16(acc[mf][nf], ah[mf], bl[nf]);
        __syncthreads();
    }
#undef G_LDGX
#undef G_STSX
#undef G_CPAW

#pragma unroll
    for (int mf = 0; mf < 4; mf++) {
#pragma unroll
        for (int h2 = 0; h2 < 2; h2++) {
            const int i = i0 + wi * 64 + mf * 16 + g + h2 * 8;
            const size_t rb = (size_t)i * HQ;
#pragma unroll
            for (int nf = 0; nf < 4; nf++) {
                const int j = wj * 32 + nf * 8 + 2 * tq;
                const float2 bb1 = *reinterpret_cast<const float2*>(b1 + j);
                const float2 bb2 = *reinterpret_cast<const float2*>(b2 + j);
                float v0 = acc[mf][nf][h2 * 2 + 0] + bb1.x + bb2.x;
                float v1 = acc[mf][nf][h2 * 2 + 1] + bb1.y + bb2.y;
                const float2 hv = *reinterpret_cast<const float2*>(hp + rb + j);
                const float2 zz = *reinterpret_cast<const float2*>(zp + rb + j);
                float2 o;
                o.x = (1.f - zz.x) * hv.x + zz.x * tanhf(v0);
                o.y = (1.f - zz.y) * hv.y + zz.y * tanhf(v1);
                *reinterpret_cast<float2*>(outp + rb + j) = o;
            }
        }
    }
}

// ---------------------------------------------------------------------------
// Host launcher
// ---------------------------------------------------------------------------
extern "C" void kernel_launch(void* const* d_in, const int* in_sizes, int n_in,
                              void* d_out, int out_size)
{
    const float* A      = (const float*)d_in[0];
    const float* hidden = (const float*)d_in[1];
    const float* b_ah   = (const float*)d_in[2];
    const float* w_z    = (const float*)d_in[3];
    const float* b_wz   = (const float*)d_in[4];
    const float* u_z    = (const float*)d_in[5];
    const float* b_uz   = (const float*)d_in[6];
    const float* w_r    = (const float*)d_in[7];
    const float* b_wr   = (const float*)d_in[8];
    const float* u_r    = (const float*)d_in[9];
    const float* b_ur   = (const float*)d_in[10];
    const float* w      = (const float*)d_in[11];
    const float* b_w    = (const float*)d_in[12];
    const float* u      = (const float*)d_in[13];
    const float* b_u    = (const float*)d_in[14];
    float* out = (float*)d_out;

    float *ga, *gz, *grh, *h0, *h1;
    uint32_t* Wsp;
    cudaGetSymbolAddress((void**)&ga,  g_a);
    cudaGetSymbolAddress((void**)&gz,  g_z);
    cudaGetSymbolAddress((void**)&grh, g_rh);
    cudaGetSymbolAddress((void**)&h0,  g_h0);
    cudaGetSymbolAddress((void**)&h1,  g_h1);
    cudaGetSymbolAddress((void**)&Wsp, g_Wh);

    cudaFuncSetAttribute(k_mma_a, cudaFuncAttributeMaxDynamicSharedMemorySize, 34816);
    cudaFuncSetAttribute(k_zr,    cudaFuncAttributeMaxDynamicSharedMemorySize, 61440);
    cudaFuncSetAttribute(k_cgate, cudaFuncAttributeMaxDynamicSharedMemorySize, 49152);

    const int S  = HQ * HQ;      // 16384 floats per matrix
    const int SW = S / 2;        // 8192 packed words per matrix
    k_splith<<<S / 1024, 256>>>(w_z, Wsp + 0 * SW,  Wsp + 1 * SW,  S / 4);
    k_splith<<<S / 1024, 256>>>(u_z, Wsp + 2 * SW,  Wsp + 3 * SW,  S / 4);
    k_splith<<<S / 1024, 256>>>(w_r, Wsp + 4 * SW,  Wsp + 5 * SW,  S / 4);
    k_splith<<<S / 1024, 256>>>(u_r, Wsp + 6 * SW,  Wsp + 7 * SW,  S / 4);
    k_splith<<<S / 1024, 256>>>(w,   Wsp + 8 * SW,  Wsp + 9 * SW,  S / 4);
    k_splith<<<S / 1024, 256>>>(u,   Wsp + 10 * SW, Wsp + 11 * SW, S / 4);

    const float* hpr[4] = { hidden, h0, h1, h0 };
    float*       hnr[4] = { h0, h1, h0, out };

    for (int s = 0; s < 4; s++) {
        const float* hp = hpr[s];
        k_mma_a<<<dim3(4, BQ), 256, 34816>>>(A, hp, b_ah, ga);
        k_zr<<<M2 / 64, 256, 61440>>>(ga, hp, Wsp, b_wz, b_uz, b_wr, b_ur, gz, grh);
        k_cgate<<<M2 / 128, 256, 49152>>>(ga, grh, Wsp, b_w, b_u, hp, gz, hnr[s]);
    }
}